// round 1
// baseline (speedup 1.0000x reference)
#include <cuda_runtime.h>
#include <cstdint>

#define SCORE_THRESH 0.05f
#define IOU_THRESH   0.5f
#define KTOP 1000
#define KPAD 1024
#define MAXDET 100
#define MAX_A (1 << 18)   // 262144 >= 196416

// ---------------- device scratch (static; no allocations) ----------------
__device__ unsigned            g_key[MAX_A];        // sortable score key per anchor
__device__ unsigned            g_ties[MAX_A];       // anchor indices equal to pivot
__device__ unsigned long long  g_cand[KPAD];        // (key<<32)|(~idx)
__device__ unsigned long long  g_sorted[KPAD];
__device__ __align__(16) float g_sbox[KPAD * 4];    // decoded clipped boxes per slot
__device__ float               g_sscore[KPAD];
__device__ unsigned long long  g_mask[KPAD * 16];   // 1024 x 1024 suppression bits
__device__ unsigned            g_hist[256];
__device__ unsigned            g_pref;
__device__ unsigned            g_krem;
__device__ int                 g_candCount;
__device__ int                 g_tieCount;
__device__ int                 g_det[128];          // slot ids of first <=100 kept
__device__ int                 g_detCount;

// float -> order-preserving uint32 (ascending float => ascending key)
__device__ __forceinline__ unsigned f2key(float f) {
    unsigned b = __float_as_uint(f);
    return (b & 0x80000000u) ? ~b : (b | 0x80000000u);
}
__device__ __forceinline__ float key2f(unsigned k) {
    unsigned b = (k & 0x80000000u) ? (k ^ 0x80000000u) : ~k;
    return __uint_as_float(b);
}

// ---------------- kernels ----------------
__global__ void k_init() {
    int t = threadIdx.x;
    if (t < 256) g_hist[t] = 0;
    if (t == 0) {
        g_pref = 0; g_krem = KTOP;
        g_candCount = 0; g_tieCount = 0; g_detCount = 0;
    }
}

// per-anchor max over C classes -> sortable key (thresholded to -1.0)
__global__ void k_score(const float* __restrict__ cls, int A, int C) {
    int lane = threadIdx.x & 31;
    int warp = (blockIdx.x * blockDim.x + threadIdx.x) >> 5;
    int nwarps = (gridDim.x * blockDim.x) >> 5;
    bool vec = ((C & 3) == 0);
    int nf4 = C >> 2;
    for (int a = warp; a < A; a += nwarps) {
        float m = -3.402823466e38f;
        if (vec) {
            const float4* row = (const float4*)(cls + (size_t)a * C);
            for (int i = lane; i < nf4; i += 32) {
                float4 v = row[i];
                m = fmaxf(m, fmaxf(fmaxf(v.x, v.y), fmaxf(v.z, v.w)));
            }
        } else {
            const float* row = cls + (size_t)a * C;
            for (int c = lane; c < C; c += 32) m = fmaxf(m, row[c]);
        }
        #pragma unroll
        for (int o = 16; o; o >>= 1) m = fmaxf(m, __shfl_down_sync(0xFFFFFFFFu, m, o));
        if (lane == 0) {
            float s0 = (m > SCORE_THRESH) ? m : -1.0f;
            g_key[a] = f2key(s0);
        }
    }
}

__global__ void k_hist(int A, int pass) {
    __shared__ unsigned sh[256];
    for (int t = threadIdx.x; t < 256; t += blockDim.x) sh[t] = 0;
    __syncthreads();
    unsigned pref = g_pref;
    int shiftD = 24 - 8 * pass;
    int n = gridDim.x * blockDim.x;
    for (int a = blockIdx.x * blockDim.x + threadIdx.x; a < A; a += n) {
        unsigned k = g_key[a];
        bool ok = true;
        if (pass > 0) ok = ((k >> (32 - 8 * pass)) == pref);
        if (ok) atomicAdd(&sh[(k >> shiftD) & 0xFFu], 1u);
    }
    __syncthreads();
    for (int t = threadIdx.x; t < 256; t += blockDim.x)
        if (sh[t]) atomicAdd(&g_hist[t], sh[t]);
}

__global__ void k_select() {
    if (threadIdx.x == 0) {
        unsigned krem = g_krem;
        unsigned cum = 0;
        int dsel = 0;
        for (int d = 255; d >= 0; --d) {
            unsigned c = g_hist[d];
            if (cum + c >= krem) { dsel = d; break; }
            cum += c;
        }
        g_krem = krem - cum;
        g_pref = (g_pref << 8) | (unsigned)dsel;
    }
    __syncthreads();
    if (threadIdx.x < 256) g_hist[threadIdx.x] = 0;
}

__global__ void k_compact(int A) {
    unsigned pivot = g_pref;
    int n = gridDim.x * blockDim.x;
    for (int a = blockIdx.x * blockDim.x + threadIdx.x; a < A; a += n) {
        unsigned k = g_key[a];
        if (k > pivot) {
            int p = atomicAdd(&g_candCount, 1);
            g_cand[p] = ((unsigned long long)k << 32) | (0xFFFFFFFFu - (unsigned)a);
        } else if (k == pivot) {
            int t = atomicAdd(&g_tieCount, 1);
            g_ties[t] = (unsigned)a;
        }
    }
}

// pick the `need` smallest-index ties and append; pad handled in sort kernel
__global__ void k_tiesel() {
    __shared__ unsigned s[1024];
    __shared__ unsigned long long red[1024];
    int tid = threadIdx.x;
    int CA = g_candCount;
    int need = KTOP - CA;
    int T = g_tieCount;
    unsigned pivot = g_pref;
    if (need <= 0) return;
    if (T <= 1024) {
        s[tid] = (tid < T) ? g_ties[tid] : 0xFFFFFFFFu;
        __syncthreads();
        for (int k = 2; k <= 1024; k <<= 1)
            for (int j = k >> 1; j > 0; j >>= 1) {
                int ixj = tid ^ j;
                if (ixj > tid) {
                    unsigned a = s[tid], b = s[ixj];
                    bool up = ((tid & k) == 0);
                    if (up ? (a > b) : (a < b)) { s[tid] = b; s[ixj] = a; }
                }
                __syncthreads();
            }
        if (tid < need)
            g_cand[CA + tid] = ((unsigned long long)pivot << 32) | (0xFFFFFFFFu - s[tid]);
    } else {
        // degenerate slow path: iterative min-index selection
        for (int r = 0; r < need; ++r) {
            unsigned long long lm = ~0ULL;
            for (int i = tid; i < T; i += 1024) {
                unsigned long long p = ((unsigned long long)g_ties[i] << 32) | (unsigned)i;
                if (p < lm) lm = p;
            }
            red[tid] = lm;
            __syncthreads();
            for (int st = 512; st > 0; st >>= 1) {
                if (tid < st && red[tid + st] < red[tid]) red[tid] = red[tid + st];
                __syncthreads();
            }
            if (tid == 0) {
                unsigned long long m = red[0];
                unsigned idx = (unsigned)(m >> 32);
                unsigned pos = (unsigned)m;
                g_cand[CA + r] = ((unsigned long long)pivot << 32) | (0xFFFFFFFFu - idx);
                g_ties[pos] = 0xFFFFFFFFu;
            }
            __syncthreads();
        }
    }
}

// bitonic sort 1024 x u64 descending -> stable top-k order (score desc, idx asc)
__global__ void k_sort() {
    __shared__ unsigned long long s[1024];
    int tid = threadIdx.x;
    s[tid] = (tid < KTOP) ? g_cand[tid] : 0ULL;
    __syncthreads();
    for (int k = 2; k <= 1024; k <<= 1)
        for (int j = k >> 1; j > 0; j >>= 1) {
            int ixj = tid ^ j;
            if (ixj > tid) {
                unsigned long long a = s[tid], b = s[ixj];
                bool up = ((tid & k) == 0);
                if (up ? (a < b) : (a > b)) { s[tid] = b; s[ixj] = a; }
            }
            __syncthreads();
        }
    g_sorted[tid] = s[tid];
}

__global__ void k_decode(const float* __restrict__ reg, const float* __restrict__ anc,
                         const int* __restrict__ pih, const int* __restrict__ piw) {
    int s = blockIdx.x * blockDim.x + threadIdx.x;
    if (s >= KPAD) return;
    if (s < KTOP) {
        unsigned long long ck = g_sorted[s];
        unsigned key = (unsigned)(ck >> 32);
        unsigned idx = 0xFFFFFFFFu - (unsigned)(ck & 0xFFFFFFFFu);
        float score = key2f(key);
        g_sscore[s] = score;
        float4 a4 = ((const float4*)anc)[idx];
        float4 r4 = ((const float4*)reg)[idx];
        float aw = a4.z - a4.x, ah = a4.w - a4.y;
        float acx = a4.x + 0.5f * aw, acy = a4.y + 0.5f * ah;
        float dx = r4.x * 0.1f, dy = r4.y * 0.1f;
        float dw = r4.z * 0.2f, dh = r4.w * 0.2f;
        float pcx = acx + dx * aw;
        float pcy = acy + dy * ah;
        float pw = expf(dw) * aw;
        float ph = expf(dh) * ah;
        float x1 = pcx - 0.5f * pw, y1 = pcy - 0.5f * ph;
        float x2 = pcx + 0.5f * pw, y2 = pcy + 0.5f * ph;
        float W = piw ? (float)(*piw) : 1024.0f;
        float H = pih ? (float)(*pih) : 1024.0f;
        x1 = fminf(fmaxf(x1, 0.f), W);
        y1 = fminf(fmaxf(y1, 0.f), H);
        x2 = fminf(fmaxf(x2, 0.f), W);
        y2 = fminf(fmaxf(y2, 0.f), H);
        g_sbox[4 * s + 0] = x1; g_sbox[4 * s + 1] = y1;
        g_sbox[4 * s + 2] = x2; g_sbox[4 * s + 3] = y2;
    } else {
        g_sscore[s] = -1.0f;
        g_sbox[4 * s + 0] = 0.f; g_sbox[4 * s + 1] = 0.f;
        g_sbox[4 * s + 2] = 0.f; g_sbox[4 * s + 3] = 0.f;
    }
}

// suppression bitmatrix: bit j of g_mask[i*16 + cj] => IoU(i, cj*64+j) > 0.5 && (cj*64+j) > i
__global__ void k_mask() {
    __shared__ float4 cb[64];
    __shared__ float  carea[64];
    int t = threadIdx.x;                 // 64 threads
    int j0 = blockIdx.x * 64;
    int i0 = blockIdx.y * 64;
    {
        float4 b = ((const float4*)g_sbox)[j0 + t];
        cb[t] = b;
        carea[t] = fmaxf(b.z - b.x, 0.f) * fmaxf(b.w - b.y, 0.f);
    }
    __syncthreads();
    int gi = i0 + t;
    float4 rb = ((const float4*)g_sbox)[gi];
    float ra = fmaxf(rb.z - rb.x, 0.f) * fmaxf(rb.w - rb.y, 0.f);
    unsigned long long bits = 0;
    #pragma unroll 8
    for (int j = 0; j < 64; ++j) {
        int gj = j0 + j;
        if (gj > gi) {
            float4 b = cb[j];
            float xx1 = fmaxf(rb.x, b.x);
            float yy1 = fmaxf(rb.y, b.y);
            float xx2 = fminf(rb.z, b.z);
            float yy2 = fminf(rb.w, b.w);
            float inter = fmaxf(xx2 - xx1, 0.f) * fmaxf(yy2 - yy1, 0.f);
            float denom = ra + carea[j] - inter + 1e-8f;
            float iou = __fdiv_rn(inter, denom);   // IEEE div regardless of fast-math
            if (iou > IOU_THRESH) bits |= (1ULL << j);
        }
    }
    g_mask[(size_t)gi * 16 + blockIdx.x] = bits;
}

// greedy NMS scan over SMEM-resident mask; record first <=100 kept slots
__global__ void k_nms() {
    extern __shared__ unsigned long long sh[];
    unsigned long long* smask  = sh;            // 16384 words
    unsigned long long* svalid = sh + 16384;    // 16 words
    int tid = threadIdx.x;
    for (int i = tid; i < KPAD * 16; i += blockDim.x) smask[i] = g_mask[i];
    if (tid < 16) {
        unsigned long long v = 0;
        for (int b = 0; b < 64; ++b)
            if (g_sscore[tid * 64 + b] > SCORE_THRESH) v |= (1ULL << b);
        svalid[tid] = v;
    }
    __syncthreads();
    if (tid == 0) {
        unsigned long long rem[16];
        #pragma unroll
        for (int w = 0; w < 16; ++w) rem[w] = 0;
        int dc = 0;
        for (int g = 0; g < 16 && dc < MAXDET; ++g) {
            unsigned long long alive = svalid[g] & ~rem[g];
            while (alive && dc < MAXDET) {
                int b = __ffsll((long long)alive) - 1;
                int i = (g << 6) + b;
                g_det[dc++] = i;
                const unsigned long long* row = &smask[(size_t)i * 16];
                #pragma unroll
                for (int w = 0; w < 16; ++w) rem[w] |= row[w];
                unsigned long long lowmask = (b == 63) ? 0ULL : (~0ULL << (b + 1));
                alive = (svalid[g] & ~rem[g]) & lowmask;
            }
        }
        g_detCount = dc;
    }
}

// final outputs: [0:100) scores, [100:200) class (as float), [200:600) boxes
__global__ void k_final(const float* __restrict__ cls, float* __restrict__ out, int C) {
    int lane = threadIdx.x & 31;
    int w = (blockIdx.x * blockDim.x + threadIdx.x) >> 5;
    if (w >= MAXDET) return;
    int dc = g_detCount;
    if (w < dc) {
        int s = g_det[w];
        unsigned long long ck = g_sorted[s];
        unsigned idx = 0xFFFFFFFFu - (unsigned)(ck & 0xFFFFFFFFu);
        float score = g_sscore[s];
        const float* row = cls + (size_t)idx * C;
        float bv = -3.402823466e38f;
        int bi = 0;
        for (int c = lane; c < C; c += 32) {
            float v = row[c];
            if (v > bv) { bv = v; bi = c; }     // per-lane first-max
        }
        #pragma unroll
        for (int o = 16; o; o >>= 1) {
            float ov = __shfl_down_sync(0xFFFFFFFFu, bv, o);
            int   oi = __shfl_down_sync(0xFFFFFFFFu, bi, o);
            if (ov > bv || (ov == bv && oi < bi)) { bv = ov; bi = oi; }
        }
        if (lane == 0) {
            out[w] = score;
            out[100 + w] = (float)bi;
            out[200 + 4 * w + 0] = g_sbox[4 * s + 0];
            out[200 + 4 * w + 1] = g_sbox[4 * s + 1];
            out[200 + 4 * w + 2] = g_sbox[4 * s + 2];
            out[200 + 4 * w + 3] = g_sbox[4 * s + 3];
        }
    } else {
        if (lane == 0) {
            out[w] = 0.0f;
            out[100 + w] = -1.0f;
            out[200 + 4 * w + 0] = 0.0f;
            out[200 + 4 * w + 1] = 0.0f;
            out[200 + 4 * w + 2] = 0.0f;
            out[200 + 4 * w + 3] = 0.0f;
        }
    }
}

// ---------------- host launcher ----------------
extern "C" void kernel_launch(void* const* d_in, const int* in_sizes, int n_in,
                              void* d_out, int out_size) {
    const float* cls = (const float*)d_in[0];
    const float* reg = (const float*)d_in[1];
    const float* anc = (const float*)d_in[2];
    const int* ih = (n_in > 3) ? (const int*)d_in[3] : nullptr;
    const int* iw = (n_in > 4) ? (const int*)d_in[4] : nullptr;

    int A = in_sizes[1] / 4;            // regressions: [1, A, 4]
    int C = (A > 0) ? (in_sizes[0] / A) : 80;
    float* out = (float*)d_out;
    (void)out_size;

    cudaFuncSetAttribute(k_nms, cudaFuncAttributeMaxDynamicSharedMemorySize, 131200);

    k_init<<<1, 256>>>();
    k_score<<<512, 256>>>(cls, A, C);
    for (int p = 0; p < 4; ++p) {
        k_hist<<<192, 256>>>(A, p);
        k_select<<<1, 256>>>();
    }
    k_compact<<<192, 256>>>(A);
    k_tiesel<<<1, 1024>>>();
    k_sort<<<1, 1024>>>();
    k_decode<<<4, 256>>>(reg, anc, ih, iw);
    k_mask<<<dim3(16, 16), 64>>>();
    k_nms<<<1, 256, 131200>>>();
    k_final<<<4, 1024>>>(cls, out, C);
}

// round 2
// speedup vs baseline: 1.4113x; 1.4113x over previous
#include <cuda_runtime.h>
#include <cstdint>

#define SCORE_THRESH 0.05f
#define IOU_THRESH   0.5f
#define KTOP 1000
#define KPAD 1024
#define MAXDET 100
#define MAX_A (1 << 18)

// ---------------- device scratch (static; zero-initialized) ----------------
__device__ unsigned            g_key[MAX_A];
__device__ unsigned            g_ties[MAX_A];
__device__ unsigned long long  g_cand[KPAD];
__device__ unsigned long long  g_sorted[KPAD];
__device__ __align__(16) float g_sbox[KPAD * 4];
__device__ float               g_sscore[KPAD];
__device__ unsigned long long  g_mask[KPAD * 16];
__device__ unsigned            g_hist[2048];
__device__ unsigned            g_pref;
__device__ unsigned            g_krem;
__device__ int                 g_candCount;
__device__ int                 g_tieCount;
__device__ unsigned            g_tick[3];

__device__ __forceinline__ unsigned f2key(float f) {
    unsigned b = __float_as_uint(f);
    return (b & 0x80000000u) ? ~b : (b | 0x80000000u);
}
__device__ __forceinline__ float key2f(unsigned k) {
    unsigned b = (k & 0x80000000u) ? (k ^ 0x80000000u) : ~k;
    return __uint_as_float(b);
}

// parallel radix-select step over g_hist[0..bins); requires blockDim.x == 256.
// Finds largest digit d with count(keys with digit >= d in current prefix) >= krem.
__device__ void radix_select(int bins, int passIdx, int width) {
    __shared__ unsigned cnt[2048];
    __shared__ unsigned csum[256];
    __shared__ int sdsel;
    int t = threadIdx.x;
    if (t == 0) sdsel = -1;
    int per = bins >> 8;                  // 8 or 4 bins per thread
    unsigned tot = 0;
    for (int i = 0; i < per; ++i) {
        unsigned v = g_hist[t * per + i];
        g_hist[t * per + i] = 0;          // clear for next pass / next replay
        cnt[t * per + i] = v;
        tot += v;
    }
    csum[t] = tot;
    __syncthreads();
    // inclusive suffix scan of chunk totals (Hillis-Steele)
    for (int off = 1; off < 256; off <<= 1) {
        unsigned v = csum[t];
        unsigned a = (t + off < 256) ? csum[t + off] : 0u;
        __syncthreads();
        csum[t] = v + a;
        __syncthreads();
    }
    unsigned krem = (passIdx == 0) ? (unsigned)KTOP : g_krem;
    unsigned run = (t + 1 < 256) ? csum[t + 1] : 0u;   // suffix excl of my chunk
    int best = -1; unsigned accBest = 0;
    unsigned acc = run;
    for (int i = per - 1; i >= 0; --i) {
        acc += cnt[t * per + i];          // suffix-inclusive count at d = t*per+i
        if (best < 0 && acc >= krem) { best = t * per + i; accBest = acc; }
    }
    if (best >= 0) atomicMax(&sdsel, best);
    __syncthreads();
    if (best >= 0 && best == sdsel) {
        g_krem = krem - (accBest - cnt[best]);
        g_pref = (passIdx == 0) ? (unsigned)best
                                : ((g_pref << width) | (unsigned)best);
    }
}

// per-anchor class-max -> key, fused pass-0 histogram (top 11 bits) + select
__global__ void k_score(const float* __restrict__ cls, int A, int C) {
    __shared__ unsigned sh[2048];
    for (int i = threadIdx.x; i < 2048; i += blockDim.x) sh[i] = 0;
    __syncthreads();
    int lane = threadIdx.x & 31;
    int gw = (blockIdx.x * blockDim.x + threadIdx.x) >> 5;
    int nw = (gridDim.x * blockDim.x) >> 5;

    if (C == 80) {
        const float4* p = (const float4*)cls;
        for (int a0 = gw * 4; a0 < A; a0 += nw * 4) {
            float m0 = -3.402823466e38f, m1 = m0, m2 = m0, m3 = m0;
            if (lane < 20) {
                float4 v;
                v = p[(size_t)a0 * 20 + lane];
                m0 = fmaxf(fmaxf(v.x, v.y), fmaxf(v.z, v.w));
                if (a0 + 1 < A) { v = p[(size_t)(a0 + 1) * 20 + lane];
                    m1 = fmaxf(fmaxf(v.x, v.y), fmaxf(v.z, v.w)); }
                if (a0 + 2 < A) { v = p[(size_t)(a0 + 2) * 20 + lane];
                    m2 = fmaxf(fmaxf(v.x, v.y), fmaxf(v.z, v.w)); }
                if (a0 + 3 < A) { v = p[(size_t)(a0 + 3) * 20 + lane];
                    m3 = fmaxf(fmaxf(v.x, v.y), fmaxf(v.z, v.w)); }
            }
            #pragma unroll
            for (int o = 16; o; o >>= 1) {
                m0 = fmaxf(m0, __shfl_down_sync(0xFFFFFFFFu, m0, o));
                m1 = fmaxf(m1, __shfl_down_sync(0xFFFFFFFFu, m1, o));
                m2 = fmaxf(m2, __shfl_down_sync(0xFFFFFFFFu, m2, o));
                m3 = fmaxf(m3, __shfl_down_sync(0xFFFFFFFFu, m3, o));
            }
            if (lane == 0) {
                unsigned k0 = f2key(m0 > SCORE_THRESH ? m0 : -1.0f);
                g_key[a0] = k0; atomicAdd(&sh[k0 >> 21], 1u);
                if (a0 + 1 < A) { unsigned k = f2key(m1 > SCORE_THRESH ? m1 : -1.0f);
                    g_key[a0 + 1] = k; atomicAdd(&sh[k >> 21], 1u); }
                if (a0 + 2 < A) { unsigned k = f2key(m2 > SCORE_THRESH ? m2 : -1.0f);
                    g_key[a0 + 2] = k; atomicAdd(&sh[k >> 21], 1u); }
                if (a0 + 3 < A) { unsigned k = f2key(m3 > SCORE_THRESH ? m3 : -1.0f);
                    g_key[a0 + 3] = k; atomicAdd(&sh[k >> 21], 1u); }
            }
        }
    } else {
        for (int a = gw; a < A; a += nw) {
            float m = -3.402823466e38f;
            const float* row = cls + (size_t)a * C;
            for (int c = lane; c < C; c += 32) m = fmaxf(m, row[c]);
            #pragma unroll
            for (int o = 16; o; o >>= 1) m = fmaxf(m, __shfl_down_sync(0xFFFFFFFFu, m, o));
            if (lane == 0) {
                unsigned k = f2key(m > SCORE_THRESH ? m : -1.0f);
                g_key[a] = k; atomicAdd(&sh[k >> 21], 1u);
            }
        }
    }
    __syncthreads();
    for (int i = threadIdx.x; i < 2048; i += blockDim.x) {
        unsigned v = sh[i];
        if (v) atomicAdd(&g_hist[i], v);
    }
    __threadfence();
    __syncthreads();
    __shared__ bool isLast;
    if (threadIdx.x == 0) isLast = (atomicAdd(&g_tick[0], 1u) == gridDim.x - 1);
    __syncthreads();
    if (isLast) {
        if (threadIdx.x == 0) g_tick[0] = 0;
        radix_select(2048, 0, 0);
    }
}

template<int PASS>
__global__ void k_histp(int A) {
    constexpr int bins     = (PASS == 1) ? 2048 : 1024;
    constexpr int cmpShift = (PASS == 1) ? 21 : 10;
    constexpr int digShift = (PASS == 1) ? 10 : 0;
    constexpr int width    = (PASS == 1) ? 11 : 10;
    __shared__ unsigned sh[bins];
    for (int i = threadIdx.x; i < bins; i += blockDim.x) sh[i] = 0;
    __syncthreads();
    unsigned pref = g_pref;
    int n = gridDim.x * blockDim.x;
    for (int a = blockIdx.x * blockDim.x + threadIdx.x; a < A; a += n) {
        unsigned k = g_key[a];
        if ((k >> cmpShift) == pref)
            atomicAdd(&sh[(k >> digShift) & (bins - 1)], 1u);
    }
    __syncthreads();
    for (int i = threadIdx.x; i < bins; i += blockDim.x) {
        unsigned v = sh[i];
        if (v) atomicAdd(&g_hist[i], v);
    }
    __threadfence();
    __syncthreads();
    __shared__ bool isLast;
    if (threadIdx.x == 0) isLast = (atomicAdd(&g_tick[PASS], 1u) == gridDim.x - 1);
    __syncthreads();
    if (isLast) {
        if (threadIdx.x == 0) {
            g_tick[PASS] = 0;
            if (PASS == 2) { g_candCount = 0; g_tieCount = 0; }
        }
        radix_select(bins, PASS, width);
    }
}

__global__ void k_compact(int A) {
    unsigned pivot = g_pref;
    int n = gridDim.x * blockDim.x;
    for (int a = blockIdx.x * blockDim.x + threadIdx.x; a < A; a += n) {
        unsigned k = g_key[a];
        if (k > pivot) {
            int p = atomicAdd(&g_candCount, 1);
            g_cand[p] = ((unsigned long long)k << 32) | (0xFFFFFFFFu - (unsigned)a);
        } else if (k == pivot) {
            int t = atomicAdd(&g_tieCount, 1);
            g_ties[t] = (unsigned)a;
        }
    }
}

// fused: tie selection + 1024-wide bitonic sort + box decode (1 block, 1024 thr)
__global__ void k_prep(const float* __restrict__ reg, const float* __restrict__ anc,
                       const int* __restrict__ pih, const int* __restrict__ piw) {
    __shared__ unsigned long long s64[1024];
    __shared__ unsigned s32[1024];
    int tid = threadIdx.x;
    int CA = g_candCount, T = g_tieCount, need = KTOP - CA;
    unsigned pivot = g_pref;
    if (need > 0) {
        if (T <= 1024) {
            s32[tid] = (tid < T) ? g_ties[tid] : 0xFFFFFFFFu;
            __syncthreads();
            for (int k = 2; k <= 1024; k <<= 1)
                for (int j = k >> 1; j > 0; j >>= 1) {
                    int ixj = tid ^ j;
                    if (ixj > tid) {
                        unsigned a = s32[tid], b = s32[ixj];
                        bool up = ((tid & k) == 0);
                        if (up ? (a > b) : (a < b)) { s32[tid] = b; s32[ixj] = a; }
                    }
                    __syncthreads();
                }
            if (tid < need)
                g_cand[CA + tid] = ((unsigned long long)pivot << 32) | (0xFFFFFFFFu - s32[tid]);
        } else {
            for (int r = 0; r < need; ++r) {
                unsigned long long lm = ~0ULL;
                for (int i = tid; i < T; i += 1024) {
                    unsigned long long pz = ((unsigned long long)g_ties[i] << 32) | (unsigned)i;
                    if (pz < lm) lm = pz;
                }
                s64[tid] = lm; __syncthreads();
                for (int st = 512; st > 0; st >>= 1) {
                    if (tid < st && s64[tid + st] < s64[tid]) s64[tid] = s64[tid + st];
                    __syncthreads();
                }
                if (tid == 0) {
                    unsigned long long mv = s64[0];
                    unsigned idx = (unsigned)(mv >> 32), pos = (unsigned)mv;
                    g_cand[CA + r] = ((unsigned long long)pivot << 32) | (0xFFFFFFFFu - idx);
                    g_ties[pos] = 0xFFFFFFFFu;
                }
                __syncthreads();
            }
        }
    }
    __syncthreads();
    s64[tid] = (tid < KTOP) ? g_cand[tid] : 0ULL;
    __syncthreads();
    for (int k = 2; k <= 1024; k <<= 1)
        for (int j = k >> 1; j > 0; j >>= 1) {
            int ixj = tid ^ j;
            if (ixj > tid) {
                unsigned long long a = s64[tid], b = s64[ixj];
                bool up = ((tid & k) == 0);
                if (up ? (a < b) : (a > b)) { s64[tid] = b; s64[ixj] = a; }
            }
            __syncthreads();
        }
    unsigned long long ck = s64[tid];
    g_sorted[tid] = ck;
    if (tid < KTOP) {
        unsigned key = (unsigned)(ck >> 32);
        unsigned idx = 0xFFFFFFFFu - (unsigned)(ck & 0xFFFFFFFFu);
        g_sscore[tid] = key2f(key);
        float4 a4 = ((const float4*)anc)[idx];
        float4 r4 = ((const float4*)reg)[idx];
        float aw = a4.z - a4.x, ah = a4.w - a4.y;
        float acx = a4.x + 0.5f * aw, acy = a4.y + 0.5f * ah;
        float pcx = acx + (r4.x * 0.1f) * aw;
        float pcy = acy + (r4.y * 0.1f) * ah;
        float pw = expf(r4.z * 0.2f) * aw;
        float ph = expf(r4.w * 0.2f) * ah;
        float x1 = pcx - 0.5f * pw, y1 = pcy - 0.5f * ph;
        float x2 = pcx + 0.5f * pw, y2 = pcy + 0.5f * ph;
        float W = piw ? (float)(*piw) : 1024.0f;
        float H = pih ? (float)(*pih) : 1024.0f;
        x1 = fminf(fmaxf(x1, 0.f), W); y1 = fminf(fmaxf(y1, 0.f), H);
        x2 = fminf(fmaxf(x2, 0.f), W); y2 = fminf(fmaxf(y2, 0.f), H);
        g_sbox[4 * tid + 0] = x1; g_sbox[4 * tid + 1] = y1;
        g_sbox[4 * tid + 2] = x2; g_sbox[4 * tid + 3] = y2;
    } else {
        g_sscore[tid] = -1.0f;
        g_sbox[4 * tid + 0] = 0.f; g_sbox[4 * tid + 1] = 0.f;
        g_sbox[4 * tid + 2] = 0.f; g_sbox[4 * tid + 3] = 0.f;
    }
}

__global__ void k_mask() {
    __shared__ float4 cb[64];
    __shared__ float  carea[64];
    int t = threadIdx.x;
    int j0 = blockIdx.x * 64;
    int i0 = blockIdx.y * 64;
    {
        float4 b = ((const float4*)g_sbox)[j0 + t];
        cb[t] = b;
        carea[t] = fmaxf(b.z - b.x, 0.f) * fmaxf(b.w - b.y, 0.f);
    }
    __syncthreads();
    int gi = i0 + t;
    float4 rb = ((const float4*)g_sbox)[gi];
    float ra = fmaxf(rb.z - rb.x, 0.f) * fmaxf(rb.w - rb.y, 0.f);
    unsigned long long bits = 0;
    #pragma unroll 8
    for (int j = 0; j < 64; ++j) {
        int gj = j0 + j;
        if (gj > gi) {
            float4 b = cb[j];
            float xx1 = fmaxf(rb.x, b.x);
            float yy1 = fmaxf(rb.y, b.y);
            float xx2 = fminf(rb.z, b.z);
            float yy2 = fminf(rb.w, b.w);
            float inter = fmaxf(xx2 - xx1, 0.f) * fmaxf(yy2 - yy1, 0.f);
            float denom = ra + carea[j] - inter + 1e-8f;
            float iou = __fdiv_rn(inter, denom);
            if (iou > IOU_THRESH) bits |= (1ULL << j);
        }
    }
    g_mask[(size_t)gi * 16 + blockIdx.x] = bits;
}

// fused NMS scan (warp-parallel) + final output (1 block, 1024 threads)
__global__ void k_nmsfinal(const float* __restrict__ cls, float* __restrict__ out, int C) {
    extern __shared__ unsigned long long smask[];   // 16384 u64 = 128 KB
    __shared__ unsigned sval32[32];
    __shared__ int sdet[128];
    __shared__ int sdc;
    int tid = threadIdx.x;
    for (int i = tid; i < KPAD * 16; i += 1024) smask[i] = g_mask[i];
    {
        unsigned m = __ballot_sync(0xFFFFFFFFu, g_sscore[tid] > SCORE_THRESH);
        if ((tid & 31) == 0) sval32[tid >> 5] = m;
    }
    __syncthreads();
    if (tid < 32) {
        int lane = tid;
        unsigned long long valid = 0;
        if (lane < 16)
            valid = (unsigned long long)sval32[2 * lane] |
                    ((unsigned long long)sval32[2 * lane + 1] << 32);
        unsigned long long rem = 0;
        int dc = 0;
        while (dc < MAXDET) {
            unsigned long long alive = valid & ~rem;
            unsigned ball = __ballot_sync(0xFFFFFFFFu, alive != 0ULL);
            if (!ball) break;
            int g = __ffs(ball) - 1;
            unsigned long long ga = __shfl_sync(0xFFFFFFFFu, alive, g);
            int b = __ffsll((long long)ga) - 1;
            int i = (g << 6) + b;
            if (lane == 0) sdet[dc] = i;
            dc++;
            if (lane == g) valid &= ~(1ULL << b);
            if (lane < 16) rem |= smask[(size_t)i * 16 + lane];
        }
        if (lane == 0) sdc = dc;
    }
    __syncthreads();
    int lane = tid & 31;
    int warp = tid >> 5;
    int dc = sdc;
    for (int w = warp; w < MAXDET; w += 32) {
        if (w < dc) {
            int s = sdet[w];
            unsigned long long ck = g_sorted[s];
            unsigned idx = 0xFFFFFFFFu - (unsigned)(ck & 0xFFFFFFFFu);
            const float* row = cls + (size_t)idx * C;
            float bv = -3.402823466e38f; int bi = 0;
            for (int c = lane; c < C; c += 32) {
                float v = row[c];
                if (v > bv) { bv = v; bi = c; }
            }
            #pragma unroll
            for (int o = 16; o; o >>= 1) {
                float ov = __shfl_down_sync(0xFFFFFFFFu, bv, o);
                int   oi = __shfl_down_sync(0xFFFFFFFFu, bi, o);
                if (ov > bv || (ov == bv && oi < bi)) { bv = ov; bi = oi; }
            }
            if (lane == 0) {
                out[w] = g_sscore[s];
                out[100 + w] = (float)bi;
                out[200 + 4 * w + 0] = g_sbox[4 * s + 0];
                out[200 + 4 * w + 1] = g_sbox[4 * s + 1];
                out[200 + 4 * w + 2] = g_sbox[4 * s + 2];
                out[200 + 4 * w + 3] = g_sbox[4 * s + 3];
            }
        } else if (lane == 0) {
            out[w] = 0.0f;
            out[100 + w] = -1.0f;
            out[200 + 4 * w + 0] = 0.0f; out[200 + 4 * w + 1] = 0.0f;
            out[200 + 4 * w + 2] = 0.0f; out[200 + 4 * w + 3] = 0.0f;
        }
    }
}

// ---------------- host launcher ----------------
extern "C" void kernel_launch(void* const* d_in, const int* in_sizes, int n_in,
                              void* d_out, int out_size) {
    const float* cls = (const float*)d_in[0];
    const float* reg = (const float*)d_in[1];
    const float* anc = (const float*)d_in[2];
    const int* ih = (n_in > 3) ? (const int*)d_in[3] : nullptr;
    const int* iw = (n_in > 4) ? (const int*)d_in[4] : nullptr;

    int A = in_sizes[1] / 4;
    int C = (A > 0) ? (in_sizes[0] / A) : 80;
    float* out = (float*)d_out;
    (void)out_size;

    cudaFuncSetAttribute(k_nmsfinal, cudaFuncAttributeMaxDynamicSharedMemorySize, 131072);

    k_score<<<592, 256>>>(cls, A, C);
    k_histp<1><<<192, 256>>>(A);
    k_histp<2><<<192, 256>>>(A);
    k_compact<<<192, 256>>>(A);
    k_prep<<<1, 1024>>>(reg, anc, ih, iw);
    k_mask<<<dim3(16, 16), 64>>>();
    k_nmsfinal<<<1, 1024, 131072>>>(cls, out, C);
}

// round 3
// speedup vs baseline: 1.7929x; 1.2704x over previous
#include <cuda_runtime.h>
#include <cstdint>

#define SCORE_THRESH 0.05f
#define IOU_THRESH   0.5f
#define KTOP 1000
#define KPAD 1024
#define MAXDET 100
#define MAX_A (1 << 18)
#define NBLK 148
#define NTHR 1024
#define DSMEM_BYTES 131072

// ---------------- device scratch (static; zero-initialized at load) --------
__device__ unsigned            g_key[MAX_A];
__device__ unsigned            g_ties[MAX_A];
__device__ unsigned long long  g_cand[KPAD];
__device__ unsigned            g_hist0[2048];
__device__ unsigned            g_hist1[2048];
__device__ unsigned            g_hist2[1024];
__device__ int                 g_candCount;
__device__ int                 g_tieCount;
__device__ unsigned            g_maskR[KPAD * 32];   // rank-space suppression bits
__device__ float               g_rscore[KPAD];
__device__ unsigned            g_ridx[KPAD];
__device__ __align__(16) float g_rbox[KPAD * 4];
__device__ unsigned            g_barGen;
__device__ unsigned            g_barCnt;

__device__ __forceinline__ unsigned f2key(float f) {
    unsigned b = __float_as_uint(f);
    return (b & 0x80000000u) ? ~b : (b | 0x80000000u);
}
__device__ __forceinline__ float key2f(unsigned k) {
    unsigned b = (k & 0x80000000u) ? (k ^ 0x80000000u) : ~k;
    return __uint_as_float(b);
}

// grid barrier: all NBLK blocks co-resident (1 block/SM), ticket + generation
__device__ __forceinline__ void gsync() {
    __syncthreads();
    if (threadIdx.x == 0) {
        volatile unsigned* vg = &g_barGen;
        unsigned gen = *vg;
        __threadfence();
        if (atomicAdd(&g_barCnt, 1u) == NBLK - 1) {
            atomicExch(&g_barCnt, 0u);
            __threadfence();
            atomicAdd(&g_barGen, 1u);
        } else {
            while (*vg == gen) __nanosleep(64);
        }
        __threadfence();
    }
    __syncthreads();
}

// block-local radix select over a global histogram (read-only, redundant
// per block -> deterministic identical results). bins = 2048 or 1024.
// csum: smem[1024]. Outputs via shared pointers.
__device__ void block_select(const unsigned* hist, int bins, unsigned krem,
                             unsigned* csum, int* psel,
                             unsigned* pdig, unsigned* pkrem) {
    int t = threadIdx.x;
    int per = bins >> 10;  // 2 or 1
    unsigned c0, c1 = 0;
    if (per == 2) { c0 = hist[2 * t]; c1 = hist[2 * t + 1]; }
    else          { c0 = hist[t]; }
    if (t == 0) *psel = -1;
    csum[t] = c0 + c1;
    __syncthreads();
    // inclusive suffix scan (Hillis-Steele)
    for (int off = 1; off < 1024; off <<= 1) {
        unsigned v = csum[t];
        unsigned a = (t + off < 1024) ? csum[t + off] : 0u;
        __syncthreads();
        csum[t] = v + a;
        __syncthreads();
    }
    unsigned suff = (t + 1 < 1024) ? csum[t + 1] : 0u;
    int best = -1; unsigned accAt = 0, cntAt = 0;
    unsigned acc = suff;
    if (per == 2) {
        acc += c1;
        if (acc >= krem) { best = 2 * t + 1; accAt = acc; cntAt = c1; }
        else { acc += c0; if (acc >= krem) { best = 2 * t; accAt = acc; cntAt = c0; } }
    } else {
        acc += c0;
        if (acc >= krem) { best = t; accAt = acc; cntAt = c0; }
    }
    if (best >= 0) atomicMax(psel, best);
    __syncthreads();
    if (best >= 0 && best == *psel) {
        *pdig = (unsigned)best;
        *pkrem = krem - (accAt - cntAt);
    }
    __syncthreads();
}

__global__ void __launch_bounds__(NTHR, 1)
fused(const float* __restrict__ cls, const float* __restrict__ reg,
      const float* __restrict__ anc, const int* __restrict__ pih,
      const int* __restrict__ piw, float* __restrict__ out, int A, int C) {
    extern __shared__ unsigned char dsm[];
    __shared__ int      s_sel;
    __shared__ unsigned s_dig;
    __shared__ unsigned s_krem;
    __shared__ int      s_dc;
    __shared__ int      s_det[128];

    const int tid = threadIdx.x;
    const int bid = blockIdx.x;

    // =================== P0: score + pass-0 histogram =====================
    {
        unsigned* sh = (unsigned*)dsm;          // 2048 bins
        for (int i = tid; i < 2048; i += NTHR) sh[i] = 0;
        __syncthreads();
        int lane = tid & 31;
        int gw = bid * (NTHR / 32) + (tid >> 5);
        int nw = NBLK * (NTHR / 32);
        if (C == 80) {
            const float4* p = (const float4*)cls;
            for (int a0 = gw * 4; a0 < A; a0 += nw * 4) {
                float m0 = -3.402823466e38f, m1 = m0, m2 = m0, m3 = m0;
                if (lane < 20) {
                    float4 v = p[(size_t)a0 * 20 + lane];
                    m0 = fmaxf(fmaxf(v.x, v.y), fmaxf(v.z, v.w));
                    if (a0 + 1 < A) { v = p[(size_t)(a0 + 1) * 20 + lane];
                        m1 = fmaxf(fmaxf(v.x, v.y), fmaxf(v.z, v.w)); }
                    if (a0 + 2 < A) { v = p[(size_t)(a0 + 2) * 20 + lane];
                        m2 = fmaxf(fmaxf(v.x, v.y), fmaxf(v.z, v.w)); }
                    if (a0 + 3 < A) { v = p[(size_t)(a0 + 3) * 20 + lane];
                        m3 = fmaxf(fmaxf(v.x, v.y), fmaxf(v.z, v.w)); }
                }
                #pragma unroll
                for (int o = 16; o; o >>= 1) {
                    m0 = fmaxf(m0, __shfl_down_sync(0xFFFFFFFFu, m0, o));
                    m1 = fmaxf(m1, __shfl_down_sync(0xFFFFFFFFu, m1, o));
                    m2 = fmaxf(m2, __shfl_down_sync(0xFFFFFFFFu, m2, o));
                    m3 = fmaxf(m3, __shfl_down_sync(0xFFFFFFFFu, m3, o));
                }
                if (lane == 0) {
                    unsigned k0 = f2key(m0 > SCORE_THRESH ? m0 : -1.0f);
                    g_key[a0] = k0; atomicAdd(&sh[k0 >> 21], 1u);
                    if (a0 + 1 < A) { unsigned k = f2key(m1 > SCORE_THRESH ? m1 : -1.0f);
                        g_key[a0 + 1] = k; atomicAdd(&sh[k >> 21], 1u); }
                    if (a0 + 2 < A) { unsigned k = f2key(m2 > SCORE_THRESH ? m2 : -1.0f);
                        g_key[a0 + 2] = k; atomicAdd(&sh[k >> 21], 1u); }
                    if (a0 + 3 < A) { unsigned k = f2key(m3 > SCORE_THRESH ? m3 : -1.0f);
                        g_key[a0 + 3] = k; atomicAdd(&sh[k >> 21], 1u); }
                }
            }
        } else {
            for (int a = gw; a < A; a += nw) {
                float m = -3.402823466e38f;
                const float* row = cls + (size_t)a * C;
                for (int c = lane; c < C; c += 32) m = fmaxf(m, row[c]);
                #pragma unroll
                for (int o = 16; o; o >>= 1) m = fmaxf(m, __shfl_down_sync(0xFFFFFFFFu, m, o));
                if (lane == 0) {
                    unsigned k = f2key(m > SCORE_THRESH ? m : -1.0f);
                    g_key[a] = k; atomicAdd(&sh[k >> 21], 1u);
                }
            }
        }
        __syncthreads();
        for (int i = tid; i < 2048; i += NTHR) {
            unsigned v = sh[i];
            if (v) atomicAdd(&g_hist0[i], v);
        }
    }
    gsync();  // 1

    unsigned pref0, krem1;
    // =================== P1: select0 + pass-1 histogram ===================
    {
        unsigned* csum = (unsigned*)(dsm + 8192);
        block_select(g_hist0, 2048, KTOP, csum, &s_sel, &s_dig, &s_krem);
        pref0 = s_dig; krem1 = s_krem;
        unsigned* sh = (unsigned*)dsm;
        for (int i = tid; i < 2048; i += NTHR) sh[i] = 0;
        __syncthreads();
        for (int a = bid * NTHR + tid; a < A; a += NBLK * NTHR) {
            unsigned k = g_key[a];
            if ((k >> 21) == pref0) atomicAdd(&sh[(k >> 10) & 0x7FFu], 1u);
        }
        __syncthreads();
        for (int i = tid; i < 2048; i += NTHR) {
            unsigned v = sh[i];
            if (v) atomicAdd(&g_hist1[i], v);
        }
    }
    gsync();  // 2

    unsigned pref21, krem2;
    // =================== P2: select1 + pass-2 histogram ===================
    {
        unsigned* csum = (unsigned*)(dsm + 8192);
        block_select(g_hist1, 2048, krem1, csum, &s_sel, &s_dig, &s_krem);
        pref21 = (pref0 << 11) | s_dig; krem2 = s_krem;
        unsigned* sh = (unsigned*)dsm;
        for (int i = tid; i < 1024; i += NTHR) sh[i] = 0;
        __syncthreads();
        for (int a = bid * NTHR + tid; a < A; a += NBLK * NTHR) {
            unsigned k = g_key[a];
            if ((k >> 10) == pref21) atomicAdd(&sh[k & 0x3FFu], 1u);
        }
        __syncthreads();
        for (int i = tid; i < 1024; i += NTHR) {
            unsigned v = sh[i];
            if (v) atomicAdd(&g_hist2[i], v);
        }
    }
    gsync();  // 3

    unsigned pivot;
    // =================== P3: select2 + compact ============================
    {
        unsigned* csum = (unsigned*)(dsm + 8192);
        block_select(g_hist2, 1024, krem2, csum, &s_sel, &s_dig, &s_krem);
        pivot = (pref21 << 10) | s_dig;
        for (int a = bid * NTHR + tid; a < A; a += NBLK * NTHR) {
            unsigned k = g_key[a];
            if (k > pivot) {
                int p = atomicAdd(&g_candCount, 1);
                g_cand[p] = ((unsigned long long)k << 32) | (0xFFFFFFFFu - (unsigned)a);
            } else if (k == pivot) {
                int t2 = atomicAdd(&g_tieCount, 1);
                g_ties[t2] = (unsigned)a;
            }
        }
    }
    gsync();  // 4

    // ===== P4: redundant tie-select + sort (+ decode); mask in rank space ==
    {
        // clear histograms for the next graph replay (no reader in P4/P5)
        for (int i = bid * NTHR + tid; i < 2048; i += NBLK * NTHR) g_hist0[i] = 0;
        for (int i = bid * NTHR + tid; i < 2048; i += NBLK * NTHR) g_hist1[i] = 0;
        for (int i = bid * NTHR + tid; i < 1024; i += NBLK * NTHR) g_hist2[i] = 0;

        unsigned long long* scand = (unsigned long long*)dsm;          // 8KB
        unsigned* sties = (unsigned*)(dsm + 8192);                     // 4KB
        float4*   sbox  = (float4*)(dsm + 16384);                      // 16KB
        float*    sarea = (float*)(dsm + 32768);                       // 4KB

        int CA = g_candCount;
        int T  = g_tieCount;
        int need = KTOP - CA;
        unsigned long long pivKey = ((unsigned long long)pivot << 32);

        scand[tid] = (tid < CA) ? g_cand[tid] : 0ULL;
        __syncthreads();
        if (need > 0) {
            if (T <= 1024) {
                sties[tid] = (tid < T) ? g_ties[tid] : 0xFFFFFFFFu;
                __syncthreads();
                for (int k = 2; k <= 1024; k <<= 1)
                    for (int j = k >> 1; j > 0; j >>= 1) {
                        int ixj = tid ^ j;
                        if (ixj > tid) {
                            unsigned a = sties[tid], b = sties[ixj];
                            bool up = ((tid & k) == 0);
                            if (up ? (a > b) : (a < b)) { sties[tid] = b; sties[ixj] = a; }
                        }
                        __syncthreads();
                    }
                if (tid < need)
                    scand[CA + tid] = pivKey | (0xFFFFFFFFu - sties[tid]);
            } else {
                // degenerate slow path: select `need` smallest tie indices
                unsigned* red = (unsigned*)(dsm + 8192);
                unsigned prev = 0; bool first = true;
                for (int r2 = 0; r2 < need; ++r2) {
                    unsigned lm = 0xFFFFFFFFu;
                    for (int i = tid; i < T; i += NTHR) {
                        unsigned v = g_ties[i];
                        if ((first || v > prev) && v < lm) lm = v;
                    }
                    red[tid] = lm;
                    __syncthreads();
                    for (int st = 512; st; st >>= 1) {
                        if (tid < st) red[tid] = min(red[tid], red[tid + st]);
                        __syncthreads();
                    }
                    prev = red[0]; first = false;
                    if (tid == 0) scand[CA + r2] = pivKey | (0xFFFFFFFFu - prev);
                    __syncthreads();
                }
            }
        }
        __syncthreads();
        // bitonic sort u64 descending (score desc, index asc)
        for (int k = 2; k <= 1024; k <<= 1)
            for (int j = k >> 1; j > 0; j >>= 1) {
                int ixj = tid ^ j;
                if (ixj > tid) {
                    unsigned long long a = scand[tid], b = scand[ixj];
                    bool up = ((tid & k) == 0);
                    if (up ? (a < b) : (a > b)) { scand[tid] = b; scand[ixj] = a; }
                }
                __syncthreads();
            }
        // decode box per rank (tid == rank)
        unsigned long long ck = scand[tid];
        float score; float4 box; unsigned idx = 0;
        if (ck != 0ULL) {
            unsigned key = (unsigned)(ck >> 32);
            idx = 0xFFFFFFFFu - (unsigned)(ck & 0xFFFFFFFFu);
            score = key2f(key);
            float4 a4 = ((const float4*)anc)[idx];
            float4 r4 = ((const float4*)reg)[idx];
            float aw = a4.z - a4.x, ah = a4.w - a4.y;
            float acx = a4.x + 0.5f * aw, acy = a4.y + 0.5f * ah;
            float pcx = acx + (r4.x * 0.1f) * aw;
            float pcy = acy + (r4.y * 0.1f) * ah;
            float pw = expf(r4.z * 0.2f) * aw;
            float ph = expf(r4.w * 0.2f) * ah;
            float W = (float)(*piw);
            float H = (float)(*pih);
            box.x = fminf(fmaxf(pcx - 0.5f * pw, 0.f), W);
            box.y = fminf(fmaxf(pcy - 0.5f * ph, 0.f), H);
            box.z = fminf(fmaxf(pcx + 0.5f * pw, 0.f), W);
            box.w = fminf(fmaxf(pcy + 0.5f * ph, 0.f), H);
        } else {
            score = -1.0f;
            box.x = box.y = box.z = box.w = 0.f;
        }
        sbox[tid] = box;
        sarea[tid] = fmaxf(box.z - box.x, 0.f) * fmaxf(box.w - box.y, 0.f);
        if (bid == 0) {
            g_rscore[tid] = score;
            g_ridx[tid] = idx;
            ((float4*)g_rbox)[tid] = box;
        }
        __syncthreads();
        if (bid > 0) {
            float4 cb = sbox[tid];
            float  ca = sarea[tid];
            for (int r = bid - 1; r < KPAD; r += NBLK - 1) {
                float4 rb = sbox[r];
                float  ra = sarea[r];
                float xx1 = fmaxf(rb.x, cb.x);
                float yy1 = fmaxf(rb.y, cb.y);
                float xx2 = fminf(rb.z, cb.z);
                float yy2 = fminf(rb.w, cb.w);
                float inter = fmaxf(xx2 - xx1, 0.f) * fmaxf(yy2 - yy1, 0.f);
                float denom = ra + ca - inter + 1e-8f;
                float iou = __fdiv_rn(inter, denom);
                unsigned ball = __ballot_sync(0xFFFFFFFFu, iou > IOU_THRESH);
                if ((tid & 31) == 0) g_maskR[r * 32 + (tid >> 5)] = ball;
            }
        }
    }
    gsync();  // 5

    if (bid != 0) return;

    // =================== P5 (block 0): NMS scan + outputs =================
    {
        unsigned* smask = (unsigned*)dsm;  // 128KB: rank-space mask
        for (int i = tid; i < KPAD * 32; i += NTHR) smask[i] = g_maskR[i];
        int myvalid = (g_rscore[tid] > SCORE_THRESH) ? 1 : 0;
        int nvalid = __syncthreads_count(myvalid);   // valid = prefix of ranks
        if (tid < 32) {
            int base = tid * 32;
            unsigned alive;
            if (nvalid >= base + 32)      alive = 0xFFFFFFFFu;
            else if (nvalid <= base)      alive = 0u;
            else                          alive = (1u << (nvalid - base)) - 1u;
            unsigned rem = 0;
            int dc = 0;
            while (dc < MAXDET) {
                unsigned av = alive & ~rem;
                unsigned ball = __ballot_sync(0xFFFFFFFFu, av != 0u);
                if (!ball) break;
                int grp = __ffs(ball) - 1;
                unsigned gav = __shfl_sync(0xFFFFFFFFu, av, grp);
                int b = __ffs(gav) - 1;
                int rank = (grp << 5) + b;
                if (tid == 0) s_det[dc] = rank;
                dc++;
                if (tid == grp) alive &= ~(1u << b);
                rem |= smask[rank * 32 + tid];
            }
            if (tid == 0) s_dc = dc;
        }
        __syncthreads();
        int dc = s_dc;
        int lane = tid & 31;
        int w = tid >> 5;
        for (int d = w; d < MAXDET; d += 32) {
            if (d < dc) {
                int rank = s_det[d];
                unsigned idx = g_ridx[rank];
                const float* row = cls + (size_t)idx * C;
                float bv = -3.402823466e38f; int bi = 0;
                for (int c = lane; c < C; c += 32) {
                    float v = row[c];
                    if (v > bv) { bv = v; bi = c; }
                }
                #pragma unroll
                for (int o = 16; o; o >>= 1) {
                    float ov = __shfl_down_sync(0xFFFFFFFFu, bv, o);
                    int   oi = __shfl_down_sync(0xFFFFFFFFu, bi, o);
                    if (ov > bv || (ov == bv && oi < bi)) { bv = ov; bi = oi; }
                }
                if (lane == 0) {
                    out[d] = g_rscore[rank];
                    out[100 + d] = (float)bi;
                    out[200 + 4 * d + 0] = g_rbox[4 * rank + 0];
                    out[200 + 4 * d + 1] = g_rbox[4 * rank + 1];
                    out[200 + 4 * d + 2] = g_rbox[4 * rank + 2];
                    out[200 + 4 * d + 3] = g_rbox[4 * rank + 3];
                }
            } else if (lane == 0) {
                out[d] = 0.0f;
                out[100 + d] = -1.0f;
                out[200 + 4 * d + 0] = 0.0f; out[200 + 4 * d + 1] = 0.0f;
                out[200 + 4 * d + 2] = 0.0f; out[200 + 4 * d + 3] = 0.0f;
            }
        }
        if (tid == 0) { g_candCount = 0; g_tieCount = 0; }  // reset for replay
    }
}

// ---------------- host launcher ----------------
extern "C" void kernel_launch(void* const* d_in, const int* in_sizes, int n_in,
                              void* d_out, int out_size) {
    const float* cls = (const float*)d_in[0];
    const float* reg = (const float*)d_in[1];
    const float* anc = (const float*)d_in[2];
    const int* ih = (const int*)d_in[3];
    const int* iw = (const int*)d_in[4];

    int A = in_sizes[1] / 4;
    int C = (A > 0) ? (in_sizes[0] / A) : 80;
    float* out = (float*)d_out;
    (void)out_size; (void)n_in;

    cudaFuncSetAttribute(fused, cudaFuncAttributeMaxDynamicSharedMemorySize, DSMEM_BYTES);
    fused<<<NBLK, NTHR, DSMEM_BYTES>>>(cls, reg, anc, ih, iw, out, A, C);
}

// round 4
// speedup vs baseline: 2.0782x; 1.1591x over previous
#include <cuda_runtime.h>
#include <cstdint>

#define SCORE_THRESH 0.05f
#define IOU_THRESH   0.5f
#define KTOP 1000
#define KPAD 1024
#define MAXDET 100
#define MAX_A (1 << 18)
#define NBLK 148
#define NTHR 1024
#define DSMEM_BYTES 131072

// ---------------- device scratch ----------------
__device__ unsigned            g_key[MAX_A];
__device__ unsigned            g_ties[MAX_A];
__device__ unsigned long long  g_cand[KPAD];
__device__ unsigned short      g_perm[KPAD];         // rank -> slot
__device__ unsigned            g_hist0[2048];
__device__ unsigned            g_hist1[2048];
__device__ unsigned            g_hist2[1024];
__device__ int                 g_candCount;
__device__ int                 g_tieCount;
__device__ unsigned            g_maskR[KPAD * 32];
__device__ float               g_rscore[KPAD];
__device__ unsigned            g_ridx[KPAD];
__device__ __align__(16) float g_rbox[KPAD * 4];
__device__ unsigned            g_barGen;
__device__ unsigned            g_barCnt;

__device__ __forceinline__ unsigned f2key(float f) {
    unsigned b = __float_as_uint(f);
    return (b & 0x80000000u) ? ~b : (b | 0x80000000u);
}
__device__ __forceinline__ float key2f(unsigned k) {
    unsigned b = (k & 0x80000000u) ? (k ^ 0x80000000u) : ~k;
    return __uint_as_float(b);
}

__device__ __forceinline__ void gsync() {
    __syncthreads();
    if (threadIdx.x == 0) {
        volatile unsigned* vg = &g_barGen;
        unsigned gen = *vg;
        __threadfence();
        if (atomicAdd(&g_barCnt, 1u) == NBLK - 1) {
            atomicExch(&g_barCnt, 0u);
            __threadfence();
            atomicAdd(&g_barGen, 1u);
        } else {
            while (*vg == gen) __nanosleep(32);
        }
        __threadfence();
    }
    __syncthreads();
}

// block-local redundant radix select over a global histogram.
__device__ void block_select(const unsigned* hist, int bins, unsigned krem,
                             unsigned* csum, int* psel,
                             unsigned* pdig, unsigned* pkrem) {
    int t = threadIdx.x;
    int per = bins >> 10;
    unsigned c0, c1 = 0;
    if (per == 2) { c0 = hist[2 * t]; c1 = hist[2 * t + 1]; }
    else          { c0 = hist[t]; }
    if (t == 0) *psel = -1;
    csum[t] = c0 + c1;
    __syncthreads();
    for (int off = 1; off < 1024; off <<= 1) {
        unsigned v = csum[t];
        unsigned a = (t + off < 1024) ? csum[t + off] : 0u;
        __syncthreads();
        csum[t] = v + a;
        __syncthreads();
    }
    unsigned suff = (t + 1 < 1024) ? csum[t + 1] : 0u;
    int best = -1; unsigned accAt = 0, cntAt = 0;
    unsigned acc = suff;
    if (per == 2) {
        acc += c1;
        if (acc >= krem) { best = 2 * t + 1; accAt = acc; cntAt = c1; }
        else { acc += c0; if (acc >= krem) { best = 2 * t; accAt = acc; cntAt = c0; } }
    } else {
        acc += c0;
        if (acc >= krem) { best = t; accAt = acc; cntAt = c0; }
    }
    if (best >= 0) atomicMax(psel, best);
    __syncthreads();
    if (best >= 0 && best == *psel) {
        *pdig = (unsigned)best;
        *pkrem = krem - (accAt - cntAt);
    }
    __syncthreads();
}

__global__ void __launch_bounds__(NTHR, 1)
fused(const float* __restrict__ cls, const float* __restrict__ reg,
      const float* __restrict__ anc, const int* __restrict__ pih,
      const int* __restrict__ piw, float* __restrict__ out, int A, int C) {
    extern __shared__ unsigned char dsm[];
    __shared__ int      s_sel;
    __shared__ unsigned s_dig;
    __shared__ unsigned s_krem;
    __shared__ int      s_dc;
    __shared__ int      s_det[128];

    const int tid = threadIdx.x;
    const int bid = blockIdx.x;

    // =================== P0: score + pass-0 histogram =====================
    {
        unsigned* sh = (unsigned*)dsm;
        for (int i = tid; i < 2048; i += NTHR) sh[i] = 0;
        __syncthreads();
        int lane = tid & 31;
        int gw = bid * (NTHR / 32) + (tid >> 5);
        int nw = NBLK * (NTHR / 32);
        if (C == 80) {
            const float4* p = (const float4*)cls;
            for (int a0 = gw * 8; a0 < A; a0 += nw * 8) {
                float m[8];
                #pragma unroll
                for (int r = 0; r < 8; ++r) m[r] = -3.402823466e38f;
                if (lane < 20) {
                    #pragma unroll
                    for (int r = 0; r < 8; ++r) {
                        int a = a0 + r;
                        if (a < A) {
                            float4 v = p[(size_t)a * 20 + lane];
                            m[r] = fmaxf(fmaxf(v.x, v.y), fmaxf(v.z, v.w));
                        }
                    }
                }
                #pragma unroll
                for (int o = 16; o; o >>= 1) {
                    #pragma unroll
                    for (int r = 0; r < 8; ++r)
                        m[r] = fmaxf(m[r], __shfl_down_sync(0xFFFFFFFFu, m[r], o));
                }
                if (lane == 0) {
                    #pragma unroll
                    for (int r = 0; r < 8; ++r) {
                        int a = a0 + r;
                        if (a < A) {
                            unsigned k = f2key(m[r] > SCORE_THRESH ? m[r] : -1.0f);
                            g_key[a] = k;
                            atomicAdd(&sh[k >> 21], 1u);
                        }
                    }
                }
            }
        } else {
            for (int a = gw; a < A; a += nw) {
                float mm = -3.402823466e38f;
                const float* row = cls + (size_t)a * C;
                for (int c = lane; c < C; c += 32) mm = fmaxf(mm, row[c]);
                #pragma unroll
                for (int o = 16; o; o >>= 1) mm = fmaxf(mm, __shfl_down_sync(0xFFFFFFFFu, mm, o));
                if (lane == 0) {
                    unsigned k = f2key(mm > SCORE_THRESH ? mm : -1.0f);
                    g_key[a] = k;
                    atomicAdd(&sh[k >> 21], 1u);
                }
            }
        }
        __syncthreads();
        for (int i = tid; i < 2048; i += NTHR) {
            unsigned v = sh[i];
            if (v) atomicAdd(&g_hist0[i], v);
        }
    }
    gsync();  // 1

    unsigned pref0, krem1;
    // =================== P1: select0 + pass-1 histogram ===================
    {
        unsigned* csum = (unsigned*)(dsm + 8192);
        block_select(g_hist0, 2048, KTOP, csum, &s_sel, &s_dig, &s_krem);
        pref0 = s_dig; krem1 = s_krem;
        unsigned* sh = (unsigned*)dsm;
        for (int i = tid; i < 2048; i += NTHR) sh[i] = 0;
        __syncthreads();
        for (int a = bid * NTHR + tid; a < A; a += NBLK * NTHR) {
            unsigned k = g_key[a];
            if ((k >> 21) == pref0) atomicAdd(&sh[(k >> 10) & 0x7FFu], 1u);
        }
        __syncthreads();
        for (int i = tid; i < 2048; i += NTHR) {
            unsigned v = sh[i];
            if (v) atomicAdd(&g_hist1[i], v);
        }
    }
    gsync();  // 2

    unsigned pref21, krem2;
    // =================== P2: select1 + pass-2 histogram ===================
    {
        unsigned* csum = (unsigned*)(dsm + 8192);
        block_select(g_hist1, 2048, krem1, csum, &s_sel, &s_dig, &s_krem);
        pref21 = (pref0 << 11) | s_dig; krem2 = s_krem;
        unsigned* sh = (unsigned*)dsm;
        for (int i = tid; i < 1024; i += NTHR) sh[i] = 0;
        __syncthreads();
        for (int a = bid * NTHR + tid; a < A; a += NBLK * NTHR) {
            unsigned k = g_key[a];
            if ((k >> 10) == pref21) atomicAdd(&sh[k & 0x3FFu], 1u);
        }
        __syncthreads();
        for (int i = tid; i < 1024; i += NTHR) {
            unsigned v = sh[i];
            if (v) atomicAdd(&g_hist2[i], v);
        }
    }
    gsync();  // 3

    unsigned pivot;
    // =================== P3: select2 + compact ============================
    {
        unsigned* csum = (unsigned*)(dsm + 8192);
        block_select(g_hist2, 1024, krem2, csum, &s_sel, &s_dig, &s_krem);
        pivot = (pref21 << 10) | s_dig;
        for (int a = bid * NTHR + tid; a < A; a += NBLK * NTHR) {
            unsigned k = g_key[a];
            if (k > pivot) {
                int p = atomicAdd(&g_candCount, 1);
                g_cand[p] = ((unsigned long long)k << 32) | (0xFFFFFFFFu - (unsigned)a);
            } else if (k == pivot) {
                int t2 = atomicAdd(&g_tieCount, 1);
                g_ties[t2] = (unsigned)a;
            }
        }
    }
    gsync();  // 4

    // scand persists in smem through P4 and P5
    unsigned long long* scand = (unsigned long long*)dsm;            // 8KB
    // ===== P4: redundant tie-fill; distributed rank-by-counting ==========
    {
        unsigned* sties = (unsigned*)(dsm + 8192);                   // <=8KB
        int CA = g_candCount;
        int T  = g_tieCount;
        int need = KTOP - CA;
        unsigned long long pivKey = ((unsigned long long)pivot << 32);

        // clear histograms for next replay
        for (int i = bid * NTHR + tid; i < 2048; i += NBLK * NTHR) g_hist0[i] = 0;
        for (int i = bid * NTHR + tid; i < 2048; i += NBLK * NTHR) g_hist1[i] = 0;
        for (int i = bid * NTHR + tid; i < 1024; i += NBLK * NTHR) g_hist2[i] = 0;

        scand[tid] = (tid < CA) ? g_cand[tid]
                   : ((tid >= KTOP) ? (unsigned long long)(KPAD - tid) : 0ULL);
        if (T <= 2048) {
            if (tid < T) sties[tid] = g_ties[tid];
            if (tid + 1024 < T) sties[tid + 1024] = g_ties[tid + 1024];
            __syncthreads();
            for (int t = tid; t < T; t += NTHR) {
                unsigned v = sties[t];
                int rank = 0;
                for (int i = 0; i < T; ++i) rank += (sties[i] < v);
                if (rank < need)
                    scand[CA + rank] = pivKey | (0xFFFFFFFFu - v);
            }
            __syncthreads();
        } else {
            // degenerate: sequential min-extraction (correct, rarely hit)
            unsigned* red = (unsigned*)(dsm + 8192);
            unsigned prev = 0; bool first = true;
            for (int r2 = 0; r2 < need; ++r2) {
                unsigned lm = 0xFFFFFFFFu;
                for (int i = tid; i < T; i += NTHR) {
                    unsigned v = g_ties[i];
                    if ((first || v > prev) && v < lm) lm = v;
                }
                red[tid] = lm;
                __syncthreads();
                for (int st = 512; st; st >>= 1) {
                    if (tid < st) red[tid] = min(red[tid], red[tid + st]);
                    __syncthreads();
                }
                prev = red[0]; first = false;
                if (tid == 0) scand[CA + r2] = pivKey | (0xFFFFFFFFu - prev);
                __syncthreads();
            }
        }
        // rank-by-counting for this block's assigned slots
        #pragma unroll
        for (int j = 0; j < 7; ++j) {
            int s = bid + j * NBLK;
            bool cmp = (s < KPAD) ? (scand[tid] > scand[s]) : false;
            int rank = __syncthreads_count(cmp);
            if (tid == 0 && s < KPAD) g_perm[rank] = (unsigned short)s;
        }
    }
    gsync();  // 5

    // ===== P5: decode in rank order (redundant) + mask rows ===============
    {
        float4* sbox  = (float4*)(dsm + 16384);                      // 16KB
        float*  sarea = (float*)(dsm + 32768);                       // 4KB
        int slot = g_perm[tid];
        unsigned long long ck = scand[slot];
        float score; float4 box; unsigned idx = 0;
        if (ck >= (1ULL << 32)) {
            unsigned key = (unsigned)(ck >> 32);
            idx = 0xFFFFFFFFu - (unsigned)(ck & 0xFFFFFFFFu);
            score = key2f(key);
            float4 a4 = ((const float4*)anc)[idx];
            float4 r4 = ((const float4*)reg)[idx];
            float aw = a4.z - a4.x, ah = a4.w - a4.y;
            float acx = a4.x + 0.5f * aw, acy = a4.y + 0.5f * ah;
            float pcx = acx + (r4.x * 0.1f) * aw;
            float pcy = acy + (r4.y * 0.1f) * ah;
            float pw = expf(r4.z * 0.2f) * aw;
            float ph = expf(r4.w * 0.2f) * ah;
            float W = (float)(*piw);
            float H = (float)(*pih);
            box.x = fminf(fmaxf(pcx - 0.5f * pw, 0.f), W);
            box.y = fminf(fmaxf(pcy - 0.5f * ph, 0.f), H);
            box.z = fminf(fmaxf(pcx + 0.5f * pw, 0.f), W);
            box.w = fminf(fmaxf(pcy + 0.5f * ph, 0.f), H);
        } else {
            score = -1.0f;
            box.x = box.y = box.z = box.w = 0.f;
        }
        sbox[tid] = box;
        sarea[tid] = fmaxf(box.z - box.x, 0.f) * fmaxf(box.w - box.y, 0.f);
        if (bid == 0) {
            g_rscore[tid] = score;
            g_ridx[tid] = idx;
            ((float4*)g_rbox)[tid] = box;
        }
        __syncthreads();
        if (bid > 0) {
            float4 cb = sbox[tid];
            float  ca = sarea[tid];
            for (int r = bid - 1; r < KPAD; r += NBLK - 1) {
                float4 rb = sbox[r];
                float  ra = sarea[r];
                float xx1 = fmaxf(rb.x, cb.x);
                float yy1 = fmaxf(rb.y, cb.y);
                float xx2 = fminf(rb.z, cb.z);
                float yy2 = fminf(rb.w, cb.w);
                float inter = fmaxf(xx2 - xx1, 0.f) * fmaxf(yy2 - yy1, 0.f);
                float denom = ra + ca - inter + 1e-8f;
                float iou = __fdiv_rn(inter, denom);
                unsigned ball = __ballot_sync(0xFFFFFFFFu, iou > IOU_THRESH);
                if ((tid & 31) == 0) g_maskR[r * 32 + (tid >> 5)] = ball;
            }
        }
    }
    gsync();  // 6

    if (bid != 0) return;

    // =================== P6 (block 0): NMS scan + outputs =================
    {
        unsigned* smask = (unsigned*)dsm;  // 128KB
        for (int i = tid; i < KPAD * 32; i += NTHR) smask[i] = g_maskR[i];
        int myvalid = (g_rscore[tid] > SCORE_THRESH) ? 1 : 0;
        int nvalid = __syncthreads_count(myvalid);   // valid = rank prefix
        if (tid < 32) {
            int base = tid * 32;
            unsigned alive;
            if (nvalid >= base + 32)      alive = 0xFFFFFFFFu;
            else if (nvalid <= base)      alive = 0u;
            else                          alive = (1u << (nvalid - base)) - 1u;
            unsigned rem = 0;
            int dc = 0;
            while (dc < MAXDET) {
                unsigned av = alive & ~rem;
                unsigned ball = __ballot_sync(0xFFFFFFFFu, av != 0u);
                if (!ball) break;
                int grp = __ffs(ball) - 1;
                unsigned gav = __shfl_sync(0xFFFFFFFFu, av, grp);
                int b = __ffs(gav) - 1;
                int rank = (grp << 5) + b;
                if (tid == 0) s_det[dc] = rank;
                dc++;
                if (tid == grp) alive &= ~(1u << b);
                rem |= smask[rank * 32 + tid];
            }
            if (tid == 0) s_dc = dc;
        }
        __syncthreads();
        int dc = s_dc;
        int lane = tid & 31;
        int w = tid >> 5;
        for (int d = w; d < MAXDET; d += 32) {
            if (d < dc) {
                int rank = s_det[d];
                unsigned idx = g_ridx[rank];
                const float* row = cls + (size_t)idx * C;
                float bv = -3.402823466e38f; int bi = 0;
                for (int c = lane; c < C; c += 32) {
                    float v = row[c];
                    if (v > bv) { bv = v; bi = c; }
                }
                #pragma unroll
                for (int o = 16; o; o >>= 1) {
                    float ov = __shfl_down_sync(0xFFFFFFFFu, bv, o);
                    int   oi = __shfl_down_sync(0xFFFFFFFFu, bi, o);
                    if (ov > bv || (ov == bv && oi < bi)) { bv = ov; bi = oi; }
                }
                if (lane == 0) {
                    out[d] = g_rscore[rank];
                    out[100 + d] = (float)bi;
                    out[200 + 4 * d + 0] = g_rbox[4 * rank + 0];
                    out[200 + 4 * d + 1] = g_rbox[4 * rank + 1];
                    out[200 + 4 * d + 2] = g_rbox[4 * rank + 2];
                    out[200 + 4 * d + 3] = g_rbox[4 * rank + 3];
                }
            } else if (lane == 0) {
                out[d] = 0.0f;
                out[100 + d] = -1.0f;
                out[200 + 4 * d + 0] = 0.0f; out[200 + 4 * d + 1] = 0.0f;
                out[200 + 4 * d + 2] = 0.0f; out[200 + 4 * d + 3] = 0.0f;
            }
        }
        if (tid == 0) { g_candCount = 0; g_tieCount = 0; }
    }
}

// ---------------- host launcher ----------------
extern "C" void kernel_launch(void* const* d_in, const int* in_sizes, int n_in,
                              void* d_out, int out_size) {
    const float* cls = (const float*)d_in[0];
    const float* reg = (const float*)d_in[1];
    const float* anc = (const float*)d_in[2];
    const int* ih = (const int*)d_in[3];
    const int* iw = (const int*)d_in[4];

    int A = in_sizes[1] / 4;
    int C = (A > 0) ? (in_sizes[0] / A) : 80;
    float* out = (float*)d_out;
    (void)out_size; (void)n_in;

    cudaFuncSetAttribute(fused, cudaFuncAttributeMaxDynamicSharedMemorySize, DSMEM_BYTES);
    fused<<<NBLK, NTHR, DSMEM_BYTES>>>(cls, reg, anc, ih, iw, out, A, C);
}

// round 5
// speedup vs baseline: 2.1142x; 1.0173x over previous
#include <cuda_runtime.h>
#include <cstdint>

#define SCORE_THRESH 0.05f
#define IOU_THRESH   0.5f
#define KTOP 1000
#define KPAD 1024
#define MAXDET 100
#define MAX_A (1 << 18)
#define NBLK 148
#define NTHR 1024
#define DSMEM_BYTES 131072

// ---------------- device scratch ----------------
__device__ __align__(16) unsigned g_key[MAX_A];
__device__ unsigned            g_ties[MAX_A];
__device__ unsigned long long  g_cand[KPAD];
__device__ unsigned short      g_perm[KPAD];
__device__ unsigned            g_hist0[2048];
__device__ unsigned            g_hist1[2048];
__device__ unsigned            g_hist2[1024];
__device__ int                 g_candCount;
__device__ int                 g_tieCount;
__device__ unsigned            g_maskR[KPAD * 32];
__device__ float               g_rscore[KPAD];
__device__ unsigned            g_ridx[KPAD];
__device__ __align__(16) float g_rbox[KPAD * 4];
__device__ unsigned            g_barGen;
__device__ unsigned            g_barCnt;

__device__ __forceinline__ unsigned f2key(float f) {
    unsigned b = __float_as_uint(f);
    return (b & 0x80000000u) ? ~b : (b | 0x80000000u);
}
__device__ __forceinline__ float key2f(unsigned k) {
    unsigned b = (k & 0x80000000u) ? (k ^ 0x80000000u) : ~k;
    return __uint_as_float(b);
}

__device__ __forceinline__ void gsync() {
    __syncthreads();
    if (threadIdx.x == 0) {
        volatile unsigned* vg = &g_barGen;
        unsigned gen = *vg;
        __threadfence();
        if (atomicAdd(&g_barCnt, 1u) == NBLK - 1) {
            atomicExch(&g_barCnt, 0u);
            __threadfence();
            atomicAdd(&g_barGen, 1u);
        } else {
            while (*vg == gen) __nanosleep(32);
        }
        __threadfence();
    }
    __syncthreads();
}

__device__ void block_select(const unsigned* hist, int bins, unsigned krem,
                             unsigned* csum, int* psel,
                             unsigned* pdig, unsigned* pkrem) {
    int t = threadIdx.x;
    int per = bins >> 10;
    unsigned c0, c1 = 0;
    if (per == 2) { c0 = hist[2 * t]; c1 = hist[2 * t + 1]; }
    else          { c0 = hist[t]; }
    if (t == 0) *psel = -1;
    csum[t] = c0 + c1;
    __syncthreads();
    for (int off = 1; off < 1024; off <<= 1) {
        unsigned v = csum[t];
        unsigned a = (t + off < 1024) ? csum[t + off] : 0u;
        __syncthreads();
        csum[t] = v + a;
        __syncthreads();
    }
    unsigned suff = (t + 1 < 1024) ? csum[t + 1] : 0u;
    int best = -1; unsigned accAt = 0, cntAt = 0;
    unsigned acc = suff;
    if (per == 2) {
        acc += c1;
        if (acc >= krem) { best = 2 * t + 1; accAt = acc; cntAt = c1; }
        else { acc += c0; if (acc >= krem) { best = 2 * t; accAt = acc; cntAt = c0; } }
    } else {
        acc += c0;
        if (acc >= krem) { best = t; accAt = acc; cntAt = c0; }
    }
    if (best >= 0) atomicMax(psel, best);
    __syncthreads();
    if (best >= 0 && best == *psel) {
        *pdig = (unsigned)best;
        *pkrem = krem - (accAt - cntAt);
    }
    __syncthreads();
}

__global__ void __launch_bounds__(NTHR, 1)
fused(const float* __restrict__ cls, const float* __restrict__ reg,
      const float* __restrict__ anc, const int* __restrict__ pih,
      const int* __restrict__ piw, float* __restrict__ out, int A, int C) {
    extern __shared__ unsigned char dsm[];
    __shared__ int      s_sel;
    __shared__ unsigned s_dig;
    __shared__ unsigned s_krem;
    __shared__ int      s_dc;
    __shared__ int      s_det[128];

    const int tid = threadIdx.x;
    const int bid = blockIdx.x;

    // =================== P0: score + pass-0 histogram =====================
    {
        unsigned* sh = (unsigned*)dsm;
        for (int i = tid; i < 2048; i += NTHR) sh[i] = 0;
        __syncthreads();
        int lane = tid & 31;
        int gw = bid * (NTHR / 32) + (tid >> 5);
        int nw = NBLK * (NTHR / 32);
        if (C == 80) {
            const float4* p = (const float4*)cls;
            for (int a0 = gw * 8; a0 < A; a0 += nw * 8) {
                float m[8];
                #pragma unroll
                for (int r = 0; r < 8; ++r) m[r] = -3.402823466e38f;
                if (lane < 20) {
                    #pragma unroll
                    for (int r = 0; r < 8; ++r) {
                        int a = a0 + r;
                        if (a < A) {
                            float4 v = p[(size_t)a * 20 + lane];
                            m[r] = fmaxf(fmaxf(v.x, v.y), fmaxf(v.z, v.w));
                        }
                    }
                }
                // butterfly: all lanes end with all 8 maxima
                #pragma unroll
                for (int o = 16; o; o >>= 1) {
                    #pragma unroll
                    for (int r = 0; r < 8; ++r)
                        m[r] = fmaxf(m[r], __shfl_xor_sync(0xFFFFFFFFu, m[r], o));
                }
                if (lane < 8) {
                    float mv;
                    switch (lane) {
                        case 0: mv = m[0]; break;
                        case 1: mv = m[1]; break;
                        case 2: mv = m[2]; break;
                        case 3: mv = m[3]; break;
                        case 4: mv = m[4]; break;
                        case 5: mv = m[5]; break;
                        case 6: mv = m[6]; break;
                        default: mv = m[7]; break;
                    }
                    int a = a0 + lane;
                    bool valid = (a < A);
                    unsigned k = f2key(mv > SCORE_THRESH ? mv : -1.0f);
                    if (valid) g_key[a] = k;
                    unsigned bin = valid ? (k >> 21) : (2048u + (unsigned)lane);
                    unsigned mm = __match_any_sync(0xFFu, bin);
                    if (valid && lane == (__ffs(mm) - 1))
                        atomicAdd(&sh[bin], (unsigned)__popc(mm));
                }
            }
        } else {
            for (int a = gw; a < A; a += nw) {
                float mm2 = -3.402823466e38f;
                const float* row = cls + (size_t)a * C;
                for (int c = lane; c < C; c += 32) mm2 = fmaxf(mm2, row[c]);
                #pragma unroll
                for (int o = 16; o; o >>= 1) mm2 = fmaxf(mm2, __shfl_down_sync(0xFFFFFFFFu, mm2, o));
                if (lane == 0) {
                    unsigned k = f2key(mm2 > SCORE_THRESH ? mm2 : -1.0f);
                    g_key[a] = k;
                    atomicAdd(&sh[k >> 21], 1u);
                }
            }
        }
        __syncthreads();
        for (int i = tid; i < 2048; i += NTHR) {
            unsigned v = sh[i];
            if (v) atomicAdd(&g_hist0[i], v);
        }
    }
    gsync();  // 1

    const int A4 = A >> 2;
    const int Atail = A4 << 2;

    unsigned pref0, krem1;
    // =================== P1: select0 + pass-1 histogram ===================
    {
        unsigned* csum = (unsigned*)(dsm + 8192);
        block_select(g_hist0, 2048, KTOP, csum, &s_sel, &s_dig, &s_krem);
        pref0 = s_dig; krem1 = s_krem;
        unsigned* sh = (unsigned*)dsm;
        for (int i = tid; i < 2048; i += NTHR) sh[i] = 0;
        __syncthreads();
        const uint4* kp = (const uint4*)g_key;
        for (int i = bid * NTHR + tid; i < A4; i += NBLK * NTHR) {
            uint4 k = kp[i];
            if ((k.x >> 21) == pref0) atomicAdd(&sh[(k.x >> 10) & 0x7FFu], 1u);
            if ((k.y >> 21) == pref0) atomicAdd(&sh[(k.y >> 10) & 0x7FFu], 1u);
            if ((k.z >> 21) == pref0) atomicAdd(&sh[(k.z >> 10) & 0x7FFu], 1u);
            if ((k.w >> 21) == pref0) atomicAdd(&sh[(k.w >> 10) & 0x7FFu], 1u);
        }
        if (bid == 0) {
            for (int a = Atail + tid; a < A; a += NTHR) {
                unsigned k = g_key[a];
                if ((k >> 21) == pref0) atomicAdd(&sh[(k >> 10) & 0x7FFu], 1u);
            }
        }
        __syncthreads();
        for (int i = tid; i < 2048; i += NTHR) {
            unsigned v = sh[i];
            if (v) atomicAdd(&g_hist1[i], v);
        }
    }
    gsync();  // 2

    unsigned pref21, krem2;
    // =================== P2: select1 + pass-2 histogram ===================
    {
        unsigned* csum = (unsigned*)(dsm + 8192);
        block_select(g_hist1, 2048, krem1, csum, &s_sel, &s_dig, &s_krem);
        pref21 = (pref0 << 11) | s_dig; krem2 = s_krem;
        unsigned* sh = (unsigned*)dsm;
        for (int i = tid; i < 1024; i += NTHR) sh[i] = 0;
        __syncthreads();
        const uint4* kp = (const uint4*)g_key;
        for (int i = bid * NTHR + tid; i < A4; i += NBLK * NTHR) {
            uint4 k = kp[i];
            if ((k.x >> 10) == pref21) atomicAdd(&sh[k.x & 0x3FFu], 1u);
            if ((k.y >> 10) == pref21) atomicAdd(&sh[k.y & 0x3FFu], 1u);
            if ((k.z >> 10) == pref21) atomicAdd(&sh[k.z & 0x3FFu], 1u);
            if ((k.w >> 10) == pref21) atomicAdd(&sh[k.w & 0x3FFu], 1u);
        }
        if (bid == 0) {
            for (int a = Atail + tid; a < A; a += NTHR) {
                unsigned k = g_key[a];
                if ((k >> 10) == pref21) atomicAdd(&sh[k & 0x3FFu], 1u);
            }
        }
        __syncthreads();
        for (int i = tid; i < 1024; i += NTHR) {
            unsigned v = sh[i];
            if (v) atomicAdd(&g_hist2[i], v);
        }
    }
    gsync();  // 3

    unsigned pivot;
    // =================== P3: select2 + compact ============================
    {
        unsigned* csum = (unsigned*)(dsm + 8192);
        block_select(g_hist2, 1024, krem2, csum, &s_sel, &s_dig, &s_krem);
        pivot = (pref21 << 10) | s_dig;
        const uint4* kp = (const uint4*)g_key;
        for (int i = bid * NTHR + tid; i < A4; i += NBLK * NTHR) {
            uint4 kv = kp[i];
            unsigned base = (unsigned)(i << 2);
            #pragma unroll
            for (int c = 0; c < 4; ++c) {
                unsigned k = (c == 0) ? kv.x : (c == 1) ? kv.y : (c == 2) ? kv.z : kv.w;
                unsigned a = base + (unsigned)c;
                if (k > pivot) {
                    int p = atomicAdd(&g_candCount, 1);
                    g_cand[p] = ((unsigned long long)k << 32) | (0xFFFFFFFFu - a);
                } else if (k == pivot) {
                    int t2 = atomicAdd(&g_tieCount, 1);
                    g_ties[t2] = a;
                }
            }
        }
        if (bid == 0) {
            for (int a = Atail + tid; a < A; a += NTHR) {
                unsigned k = g_key[a];
                if (k > pivot) {
                    int p = atomicAdd(&g_candCount, 1);
                    g_cand[p] = ((unsigned long long)k << 32) | (0xFFFFFFFFu - (unsigned)a);
                } else if (k == pivot) {
                    int t2 = atomicAdd(&g_tieCount, 1);
                    g_ties[t2] = (unsigned)a;
                }
            }
        }
    }
    gsync();  // 4

    unsigned long long* scand = (unsigned long long*)dsm;            // 8KB
    // ===== P4: redundant tie-fill; distributed rank-by-counting ==========
    {
        unsigned* sties = (unsigned*)(dsm + 8192);
        int CA = g_candCount;
        int T  = g_tieCount;
        int need = KTOP - CA;
        unsigned long long pivKey = ((unsigned long long)pivot << 32);

        for (int i = bid * NTHR + tid; i < 2048; i += NBLK * NTHR) g_hist0[i] = 0;
        for (int i = bid * NTHR + tid; i < 2048; i += NBLK * NTHR) g_hist1[i] = 0;
        for (int i = bid * NTHR + tid; i < 1024; i += NBLK * NTHR) g_hist2[i] = 0;

        scand[tid] = (tid < CA) ? g_cand[tid]
                   : ((tid >= KTOP) ? (unsigned long long)(KPAD - tid) : 0ULL);
        if (T <= 2048) {
            if (tid < T) sties[tid] = g_ties[tid];
            if (tid + 1024 < T) sties[tid + 1024] = g_ties[tid + 1024];
            __syncthreads();
            for (int t = tid; t < T; t += NTHR) {
                unsigned v = sties[t];
                int rank = 0;
                for (int i = 0; i < T; ++i) rank += (sties[i] < v);
                if (rank < need)
                    scand[CA + rank] = pivKey | (0xFFFFFFFFu - v);
            }
            __syncthreads();
        } else {
            unsigned* red = (unsigned*)(dsm + 8192);
            unsigned prev = 0; bool first = true;
            for (int r2 = 0; r2 < need; ++r2) {
                unsigned lm = 0xFFFFFFFFu;
                for (int i = tid; i < T; i += NTHR) {
                    unsigned v = g_ties[i];
                    if ((first || v > prev) && v < lm) lm = v;
                }
                red[tid] = lm;
                __syncthreads();
                for (int st = 512; st; st >>= 1) {
                    if (tid < st) red[tid] = min(red[tid], red[tid + st]);
                    __syncthreads();
                }
                prev = red[0]; first = false;
                if (tid == 0) scand[CA + r2] = pivKey | (0xFFFFFFFFu - prev);
                __syncthreads();
            }
        }
        #pragma unroll
        for (int j = 0; j < 7; ++j) {
            int s = bid + j * NBLK;
            bool cmp = (s < KPAD) ? (scand[tid] > scand[s]) : false;
            int rank = __syncthreads_count(cmp);
            if (tid == 0 && s < KPAD) g_perm[rank] = (unsigned short)s;
        }
    }
    gsync();  // 5

    // ===== P5: decode in rank order (redundant) + mask rows ===============
    {
        float4* sbox  = (float4*)(dsm + 16384);
        float*  sarea = (float*)(dsm + 32768);
        int slot = g_perm[tid];
        unsigned long long ck = scand[slot];
        float score; float4 box; unsigned idx = 0;
        if (ck >= (1ULL << 32)) {
            unsigned key = (unsigned)(ck >> 32);
            idx = 0xFFFFFFFFu - (unsigned)(ck & 0xFFFFFFFFu);
            score = key2f(key);
            float4 a4 = ((const float4*)anc)[idx];
            float4 r4 = ((const float4*)reg)[idx];
            float aw = a4.z - a4.x, ah = a4.w - a4.y;
            float acx = a4.x + 0.5f * aw, acy = a4.y + 0.5f * ah;
            float pcx = acx + (r4.x * 0.1f) * aw;
            float pcy = acy + (r4.y * 0.1f) * ah;
            float pw = expf(r4.z * 0.2f) * aw;
            float ph = expf(r4.w * 0.2f) * ah;
            float W = (float)(*piw);
            float H = (float)(*pih);
            box.x = fminf(fmaxf(pcx - 0.5f * pw, 0.f), W);
            box.y = fminf(fmaxf(pcy - 0.5f * ph, 0.f), H);
            box.z = fminf(fmaxf(pcx + 0.5f * pw, 0.f), W);
            box.w = fminf(fmaxf(pcy + 0.5f * ph, 0.f), H);
        } else {
            score = -1.0f;
            box.x = box.y = box.z = box.w = 0.f;
        }
        sbox[tid] = box;
        sarea[tid] = fmaxf(box.z - box.x, 0.f) * fmaxf(box.w - box.y, 0.f);
        if (bid == 0) {
            g_rscore[tid] = score;
            g_ridx[tid] = idx;
            ((float4*)g_rbox)[tid] = box;
        }
        __syncthreads();
        if (bid > 0) {
            float4 cb = sbox[tid];
            float  ca = sarea[tid];
            for (int r = bid - 1; r < KPAD; r += NBLK - 1) {
                float4 rb = sbox[r];
                float  ra = sarea[r];
                float xx1 = fmaxf(rb.x, cb.x);
                float yy1 = fmaxf(rb.y, cb.y);
                float xx2 = fminf(rb.z, cb.z);
                float yy2 = fminf(rb.w, cb.w);
                float inter = fmaxf(xx2 - xx1, 0.f) * fmaxf(yy2 - yy1, 0.f);
                float denom = ra + ca - inter + 1e-8f;
                float iou = __fdiv_rn(inter, denom);
                unsigned ball = __ballot_sync(0xFFFFFFFFu, iou > IOU_THRESH);
                if ((tid & 31) == 0) g_maskR[r * 32 + (tid >> 5)] = ball;
            }
        }
    }
    gsync();  // 6

    if (bid != 0) return;

    // =================== P6 (block 0): NMS scan + outputs =================
    {
        unsigned* smask = (unsigned*)dsm;
        for (int i = tid; i < KPAD * 32; i += NTHR) smask[i] = g_maskR[i];
        int myvalid = (g_rscore[tid] > SCORE_THRESH) ? 1 : 0;
        int nvalid = __syncthreads_count(myvalid);
        if (tid < 32) {
            int base = tid * 32;
            unsigned alive;
            if (nvalid >= base + 32)      alive = 0xFFFFFFFFu;
            else if (nvalid <= base)      alive = 0u;
            else                          alive = (1u << (nvalid - base)) - 1u;
            unsigned rem = 0;
            int dc = 0;
            while (dc < MAXDET) {
                unsigned av = alive & ~rem;
                unsigned ball = __ballot_sync(0xFFFFFFFFu, av != 0u);
                if (!ball) break;
                int grp = __ffs(ball) - 1;
                unsigned gav = __shfl_sync(0xFFFFFFFFu, av, grp);
                int b = __ffs(gav) - 1;
                int rank = (grp << 5) + b;
                if (tid == 0) s_det[dc] = rank;
                dc++;
                if (tid == grp) alive &= ~(1u << b);
                rem |= smask[rank * 32 + tid];
            }
            if (tid == 0) s_dc = dc;
        }
        __syncthreads();
        int dc = s_dc;
        int lane = tid & 31;
        int w = tid >> 5;
        for (int d = w; d < MAXDET; d += 32) {
            if (d < dc) {
                int rank = s_det[d];
                unsigned idx = g_ridx[rank];
                const float* row = cls + (size_t)idx * C;
                float bv = -3.402823466e38f; int bi = 0;
                for (int c = lane; c < C; c += 32) {
                    float v = row[c];
                    if (v > bv) { bv = v; bi = c; }
                }
                #pragma unroll
                for (int o = 16; o; o >>= 1) {
                    float ov = __shfl_down_sync(0xFFFFFFFFu, bv, o);
                    int   oi = __shfl_down_sync(0xFFFFFFFFu, bi, o);
                    if (ov > bv || (ov == bv && oi < bi)) { bv = ov; bi = oi; }
                }
                if (lane == 0) {
                    out[d] = g_rscore[rank];
                    out[100 + d] = (float)bi;
                    out[200 + 4 * d + 0] = g_rbox[4 * rank + 0];
                    out[200 + 4 * d + 1] = g_rbox[4 * rank + 1];
                    out[200 + 4 * d + 2] = g_rbox[4 * rank + 2];
                    out[200 + 4 * d + 3] = g_rbox[4 * rank + 3];
                }
            } else if (lane == 0) {
                out[d] = 0.0f;
                out[100 + d] = -1.0f;
                out[200 + 4 * d + 0] = 0.0f; out[200 + 4 * d + 1] = 0.0f;
                out[200 + 4 * d + 2] = 0.0f; out[200 + 4 * d + 3] = 0.0f;
            }
        }
        if (tid == 0) { g_candCount = 0; g_tieCount = 0; }
    }
}

// ---------------- host launcher ----------------
extern "C" void kernel_launch(void* const* d_in, const int* in_sizes, int n_in,
                              void* d_out, int out_size) {
    const float* cls = (const float*)d_in[0];
    const float* reg = (const float*)d_in[1];
    const float* anc = (const float*)d_in[2];
    const int* ih = (const int*)d_in[3];
    const int* iw = (const int*)d_in[4];

    int A = in_sizes[1] / 4;
    int C = (A > 0) ? (in_sizes[0] / A) : 80;
    float* out = (float*)d_out;
    (void)out_size; (void)n_in;

    cudaFuncSetAttribute(fused, cudaFuncAttributeMaxDynamicSharedMemorySize, DSMEM_BYTES);
    fused<<<NBLK, NTHR, DSMEM_BYTES>>>(cls, reg, anc, ih, iw, out, A, C);
}

// round 6
// speedup vs baseline: 2.4300x; 1.1493x over previous
#include <cuda_runtime.h>
#include <cstdint>

#define SCORE_THRESH 0.05f
#define IOU_THRESH   0.5f
#define KTOP 1000
#define KPAD 1024
#define MAXDET 100
#define MAX_A (1 << 18)
#define NBLK 148
#define NTHR 1024
#define DSMEM_BYTES 131072

// ---------------- device scratch ----------------
__device__ __align__(16) unsigned g_key[MAX_A];
__device__ unsigned            g_ties[MAX_A];
__device__ unsigned long long  g_cand[KPAD];
__device__ unsigned short      g_perm[KPAD];
__device__ unsigned            g_hist0[2048];
__device__ unsigned            g_hist1[2048];
__device__ unsigned            g_hist2[1024];
__device__ int                 g_candCount;
__device__ int                 g_tieCount;
__device__ __align__(16) unsigned g_maskR[KPAD * 32];
__device__ float               g_rscore[KPAD];
__device__ unsigned            g_ridx[KPAD];
__device__ __align__(16) float g_rbox[KPAD * 4];
__device__ unsigned            g_barGen;
__device__ unsigned            g_barCnt;

__device__ __forceinline__ unsigned f2key(float f) {
    unsigned b = __float_as_uint(f);
    return (b & 0x80000000u) ? ~b : (b | 0x80000000u);
}
__device__ __forceinline__ float key2f(unsigned k) {
    unsigned b = (k & 0x80000000u) ? (k ^ 0x80000000u) : ~k;
    return __uint_as_float(b);
}

__device__ __forceinline__ void gsync() {
    __syncthreads();
    if (threadIdx.x == 0) {
        volatile unsigned* vg = &g_barGen;
        unsigned gen = *vg;
        __threadfence();
        if (atomicAdd(&g_barCnt, 1u) == NBLK - 1) {
            atomicExch(&g_barCnt, 0u);
            __threadfence();
            atomicAdd(&g_barGen, 1u);
        } else {
            while (*vg == gen) __nanosleep(32);
        }
        __threadfence();
    }
    __syncthreads();
}

__device__ void block_select(const unsigned* hist, int bins, unsigned krem,
                             unsigned* csum, int* psel,
                             unsigned* pdig, unsigned* pkrem) {
    int t = threadIdx.x;
    int per = bins >> 10;
    unsigned c0, c1 = 0;
    if (per == 2) { c0 = hist[2 * t]; c1 = hist[2 * t + 1]; }
    else          { c0 = hist[t]; }
    if (t == 0) *psel = -1;
    csum[t] = c0 + c1;
    __syncthreads();
    for (int off = 1; off < 1024; off <<= 1) {
        unsigned v = csum[t];
        unsigned a = (t + off < 1024) ? csum[t + off] : 0u;
        __syncthreads();
        csum[t] = v + a;
        __syncthreads();
    }
    unsigned suff = (t + 1 < 1024) ? csum[t + 1] : 0u;
    int best = -1; unsigned accAt = 0, cntAt = 0;
    unsigned acc = suff;
    if (per == 2) {
        acc += c1;
        if (acc >= krem) { best = 2 * t + 1; accAt = acc; cntAt = c1; }
        else { acc += c0; if (acc >= krem) { best = 2 * t; accAt = acc; cntAt = c0; } }
    } else {
        acc += c0;
        if (acc >= krem) { best = t; accAt = acc; cntAt = c0; }
    }
    if (best >= 0) atomicMax(psel, best);
    __syncthreads();
    if (best >= 0 && best == *psel) {
        *pdig = (unsigned)best;
        *pkrem = krem - (accAt - cntAt);
    }
    __syncthreads();
}

__global__ void __launch_bounds__(NTHR, 1)
fused(const float* __restrict__ cls, const float* __restrict__ reg,
      const float* __restrict__ anc, const int* __restrict__ pih,
      const int* __restrict__ piw, float* __restrict__ out, int A, int C) {
    extern __shared__ unsigned char dsm[];
    __shared__ int      s_sel;
    __shared__ unsigned s_dig;
    __shared__ unsigned s_krem;
    __shared__ int      s_dc;
    __shared__ int      s_det[128];

    const int tid = threadIdx.x;
    const int bid = blockIdx.x;

    // =================== P0: score + pass-0 histogram =====================
    {
        unsigned* sh = (unsigned*)dsm;
        for (int i = tid; i < 2048; i += NTHR) sh[i] = 0;
        __syncthreads();
        int lane = tid & 31;
        int gw = bid * (NTHR / 32) + (tid >> 5);
        int nw = NBLK * (NTHR / 32);
        if (C == 80) {
            const float4* p = (const float4*)cls;
            for (int a0 = gw * 8; a0 < A; a0 += nw * 8) {
                float m[8];
                #pragma unroll
                for (int r = 0; r < 8; ++r) m[r] = 0.0f;   // scores >= 0
                if (lane < 20) {
                    #pragma unroll
                    for (int r = 0; r < 8; ++r) {
                        int a = a0 + r;
                        if (a < A) {
                            float4 v = p[(size_t)a * 20 + lane];
                            m[r] = fmaxf(fmaxf(v.x, v.y), fmaxf(v.z, v.w));
                        }
                    }
                }
                // redux: uint order == float order for non-negative floats
                #pragma unroll
                for (int r = 0; r < 8; ++r) {
                    unsigned u = __reduce_max_sync(0xFFFFFFFFu, __float_as_uint(m[r]));
                    m[r] = __uint_as_float(u);
                }
                if (lane < 8) {
                    float mv;
                    switch (lane) {
                        case 0: mv = m[0]; break;
                        case 1: mv = m[1]; break;
                        case 2: mv = m[2]; break;
                        case 3: mv = m[3]; break;
                        case 4: mv = m[4]; break;
                        case 5: mv = m[5]; break;
                        case 6: mv = m[6]; break;
                        default: mv = m[7]; break;
                    }
                    int a = a0 + lane;
                    bool valid = (a < A);
                    unsigned k = f2key(mv > SCORE_THRESH ? mv : -1.0f);
                    if (valid) g_key[a] = k;
                    unsigned bin = valid ? (k >> 21) : (2048u + (unsigned)lane);
                    unsigned mm = __match_any_sync(0xFFu, bin);
                    if (valid && lane == (__ffs(mm) - 1))
                        atomicAdd(&sh[bin], (unsigned)__popc(mm));
                }
            }
        } else {
            for (int a = gw; a < A; a += nw) {
                float mm2 = -3.402823466e38f;
                const float* row = cls + (size_t)a * C;
                for (int c = lane; c < C; c += 32) mm2 = fmaxf(mm2, row[c]);
                #pragma unroll
                for (int o = 16; o; o >>= 1) mm2 = fmaxf(mm2, __shfl_down_sync(0xFFFFFFFFu, mm2, o));
                if (lane == 0) {
                    unsigned k = f2key(mm2 > SCORE_THRESH ? mm2 : -1.0f);
                    g_key[a] = k;
                    atomicAdd(&sh[k >> 21], 1u);
                }
            }
        }
        __syncthreads();
        for (int i = tid; i < 2048; i += NTHR) {
            unsigned v = sh[i];
            if (v) atomicAdd(&g_hist0[i], v);
        }
    }
    gsync();  // 1

    const int A4 = A >> 2;
    const int Atail = A4 << 2;

    unsigned pref0, krem1;
    // =================== P1: select0 + pass-1 histogram ===================
    {
        unsigned* csum = (unsigned*)(dsm + 8192);
        block_select(g_hist0, 2048, KTOP, csum, &s_sel, &s_dig, &s_krem);
        pref0 = s_dig; krem1 = s_krem;
        unsigned* sh = (unsigned*)dsm;
        for (int i = tid; i < 2048; i += NTHR) sh[i] = 0;
        __syncthreads();
        const uint4* kp = (const uint4*)g_key;
        for (int i = bid * NTHR + tid; i < A4; i += NBLK * NTHR) {
            uint4 k = kp[i];
            if ((k.x >> 21) == pref0) atomicAdd(&sh[(k.x >> 10) & 0x7FFu], 1u);
            if ((k.y >> 21) == pref0) atomicAdd(&sh[(k.y >> 10) & 0x7FFu], 1u);
            if ((k.z >> 21) == pref0) atomicAdd(&sh[(k.z >> 10) & 0x7FFu], 1u);
            if ((k.w >> 21) == pref0) atomicAdd(&sh[(k.w >> 10) & 0x7FFu], 1u);
        }
        if (bid == 0) {
            for (int a = Atail + tid; a < A; a += NTHR) {
                unsigned k = g_key[a];
                if ((k >> 21) == pref0) atomicAdd(&sh[(k >> 10) & 0x7FFu], 1u);
            }
        }
        __syncthreads();
        for (int i = tid; i < 2048; i += NTHR) {
            unsigned v = sh[i];
            if (v) atomicAdd(&g_hist1[i], v);
        }
    }
    gsync();  // 2

    unsigned pref21, krem2;
    // =================== P2: select1 + pass-2 histogram ===================
    {
        unsigned* csum = (unsigned*)(dsm + 8192);
        block_select(g_hist1, 2048, krem1, csum, &s_sel, &s_dig, &s_krem);
        pref21 = (pref0 << 11) | s_dig; krem2 = s_krem;
        unsigned* sh = (unsigned*)dsm;
        for (int i = tid; i < 1024; i += NTHR) sh[i] = 0;
        __syncthreads();
        const uint4* kp = (const uint4*)g_key;
        for (int i = bid * NTHR + tid; i < A4; i += NBLK * NTHR) {
            uint4 k = kp[i];
            if ((k.x >> 10) == pref21) atomicAdd(&sh[k.x & 0x3FFu], 1u);
            if ((k.y >> 10) == pref21) atomicAdd(&sh[k.y & 0x3FFu], 1u);
            if ((k.z >> 10) == pref21) atomicAdd(&sh[k.z & 0x3FFu], 1u);
            if ((k.w >> 10) == pref21) atomicAdd(&sh[k.w & 0x3FFu], 1u);
        }
        if (bid == 0) {
            for (int a = Atail + tid; a < A; a += NTHR) {
                unsigned k = g_key[a];
                if ((k >> 10) == pref21) atomicAdd(&sh[k & 0x3FFu], 1u);
            }
        }
        __syncthreads();
        for (int i = tid; i < 1024; i += NTHR) {
            unsigned v = sh[i];
            if (v) atomicAdd(&g_hist2[i], v);
        }
    }
    gsync();  // 3

    unsigned pivot;
    // =================== P3: select2 + compact ============================
    {
        unsigned* csum = (unsigned*)(dsm + 8192);
        block_select(g_hist2, 1024, krem2, csum, &s_sel, &s_dig, &s_krem);
        pivot = (pref21 << 10) | s_dig;
        const uint4* kp = (const uint4*)g_key;
        for (int i = bid * NTHR + tid; i < A4; i += NBLK * NTHR) {
            uint4 kv = kp[i];
            unsigned base = (unsigned)(i << 2);
            #pragma unroll
            for (int c = 0; c < 4; ++c) {
                unsigned k = (c == 0) ? kv.x : (c == 1) ? kv.y : (c == 2) ? kv.z : kv.w;
                unsigned a = base + (unsigned)c;
                if (k > pivot) {
                    int p = atomicAdd(&g_candCount, 1);
                    g_cand[p] = ((unsigned long long)k << 32) | (0xFFFFFFFFu - a);
                } else if (k == pivot) {
                    int t2 = atomicAdd(&g_tieCount, 1);
                    g_ties[t2] = a;
                }
            }
        }
        if (bid == 0) {
            for (int a = Atail + tid; a < A; a += NTHR) {
                unsigned k = g_key[a];
                if (k > pivot) {
                    int p = atomicAdd(&g_candCount, 1);
                    g_cand[p] = ((unsigned long long)k << 32) | (0xFFFFFFFFu - (unsigned)a);
                } else if (k == pivot) {
                    int t2 = atomicAdd(&g_tieCount, 1);
                    g_ties[t2] = (unsigned)a;
                }
            }
        }
    }
    gsync();  // 4

    unsigned long long* scand = (unsigned long long*)dsm;            // 8KB
    // ===== P4: redundant tie-fill; distributed rank-by-counting ==========
    {
        unsigned* sties = (unsigned*)(dsm + 8192);
        int CA = g_candCount;
        int T  = g_tieCount;
        int need = KTOP - CA;
        unsigned long long pivKey = ((unsigned long long)pivot << 32);

        for (int i = bid * NTHR + tid; i < 2048; i += NBLK * NTHR) g_hist0[i] = 0;
        for (int i = bid * NTHR + tid; i < 2048; i += NBLK * NTHR) g_hist1[i] = 0;
        for (int i = bid * NTHR + tid; i < 1024; i += NBLK * NTHR) g_hist2[i] = 0;

        scand[tid] = (tid < CA) ? g_cand[tid]
                   : ((tid >= KTOP) ? (unsigned long long)(KPAD - tid) : 0ULL);
        if (T <= 2048) {
            if (tid < T) sties[tid] = g_ties[tid];
            if (tid + 1024 < T) sties[tid + 1024] = g_ties[tid + 1024];
            __syncthreads();
            for (int t = tid; t < T; t += NTHR) {
                unsigned v = sties[t];
                int rank = 0;
                for (int i = 0; i < T; ++i) rank += (sties[i] < v);
                if (rank < need)
                    scand[CA + rank] = pivKey | (0xFFFFFFFFu - v);
            }
            __syncthreads();
        } else {
            unsigned* red = (unsigned*)(dsm + 8192);
            unsigned prev = 0; bool first = true;
            for (int r2 = 0; r2 < need; ++r2) {
                unsigned lm = 0xFFFFFFFFu;
                for (int i = tid; i < T; i += NTHR) {
                    unsigned v = g_ties[i];
                    if ((first || v > prev) && v < lm) lm = v;
                }
                red[tid] = lm;
                __syncthreads();
                for (int st = 512; st; st >>= 1) {
                    if (tid < st) red[tid] = min(red[tid], red[tid + st]);
                    __syncthreads();
                }
                prev = red[0]; first = false;
                if (tid == 0) scand[CA + r2] = pivKey | (0xFFFFFFFFu - prev);
                __syncthreads();
            }
        }
        #pragma unroll
        for (int j = 0; j < 7; ++j) {
            int s = bid + j * NBLK;
            bool cmp = (s < KPAD) ? (scand[tid] > scand[s]) : false;
            int rank = __syncthreads_count(cmp);
            if (tid == 0 && s < KPAD) g_perm[rank] = (unsigned short)s;
        }
    }
    gsync();  // 5

    // ===== P5: decode in rank order (redundant) + triangle mask rows ======
    {
        float4* sbox  = (float4*)(dsm + 16384);
        float*  sarea = (float*)(dsm + 32768);
        int slot = g_perm[tid];
        unsigned long long ck = scand[slot];
        float score; float4 box; unsigned idx = 0;
        if (ck >= (1ULL << 32)) {
            unsigned key = (unsigned)(ck >> 32);
            idx = 0xFFFFFFFFu - (unsigned)(ck & 0xFFFFFFFFu);
            score = key2f(key);
            float4 a4 = ((const float4*)anc)[idx];
            float4 r4 = ((const float4*)reg)[idx];
            float aw = a4.z - a4.x, ah = a4.w - a4.y;
            float acx = a4.x + 0.5f * aw, acy = a4.y + 0.5f * ah;
            float pcx = acx + (r4.x * 0.1f) * aw;
            float pcy = acy + (r4.y * 0.1f) * ah;
            float pw = expf(r4.z * 0.2f) * aw;
            float ph = expf(r4.w * 0.2f) * ah;
            float W = (float)(*piw);
            float H = (float)(*pih);
            box.x = fminf(fmaxf(pcx - 0.5f * pw, 0.f), W);
            box.y = fminf(fmaxf(pcy - 0.5f * ph, 0.f), H);
            box.z = fminf(fmaxf(pcx + 0.5f * pw, 0.f), W);
            box.w = fminf(fmaxf(pcy + 0.5f * ph, 0.f), H);
        } else {
            score = -1.0f;
            box.x = box.y = box.z = box.w = 0.f;
        }
        sbox[tid] = box;
        sarea[tid] = fmaxf(box.z - box.x, 0.f) * fmaxf(box.w - box.y, 0.f);
        if (bid == 0) {
            g_rscore[tid] = score;
            g_ridx[tid] = idx;
            ((float4*)g_rbox)[tid] = box;
        }
        __syncthreads();
        // triangle-only mask: row r gets bits only for columns tid > r
        float4 cb = sbox[tid];
        float  ca = sarea[tid];
        for (int r = bid; r < KPAD; r += NBLK) {
            bool sup = false;
            if (tid > r) {              // whole warps below diagonal skip math
                float4 rb = sbox[r];
                float  ra = sarea[r];
                float xx1 = fmaxf(rb.x, cb.x);
                float yy1 = fmaxf(rb.y, cb.y);
                float xx2 = fminf(rb.z, cb.z);
                float yy2 = fminf(rb.w, cb.w);
                float inter = fmaxf(xx2 - xx1, 0.f) * fmaxf(yy2 - yy1, 0.f);
                float denom = ra + ca - inter + 1e-8f;   // > 0 always
                sup = inter > IOU_THRESH * denom;        // == iou > thresh
            }
            unsigned ball = __ballot_sync(0xFFFFFFFFu, sup);
            if ((tid & 31) == 0) g_maskR[r * 32 + (tid >> 5)] = ball;
        }
    }
    gsync();  // 6

    if (bid != 0) return;

    // =================== P6 (block 0): NMS scan + outputs =================
    {
        unsigned* smask = (unsigned*)dsm;
        {
            const uint4* gm = (const uint4*)g_maskR;
            uint4* sm4 = (uint4*)smask;
            for (int i = tid; i < KPAD * 8; i += NTHR) sm4[i] = gm[i];
        }
        int myvalid = (g_rscore[tid] > SCORE_THRESH) ? 1 : 0;
        int nvalid = __syncthreads_count(myvalid);
        if (tid < 32) {
            int base = tid * 32;
            unsigned alive;
            if (nvalid >= base + 32)      alive = 0xFFFFFFFFu;
            else if (nvalid <= base)      alive = 0u;
            else                          alive = (1u << (nvalid - base)) - 1u;
            unsigned rem = 0;
            int dc = 0;
            while (dc < MAXDET) {
                unsigned av = alive & ~rem;
                unsigned ball = __ballot_sync(0xFFFFFFFFu, av != 0u);
                if (!ball) break;
                int grp = __ffs(ball) - 1;
                unsigned gav = __shfl_sync(0xFFFFFFFFu, av, grp);
                int b = __ffs(gav) - 1;
                int rank = (grp << 5) + b;
                if (tid == 0) s_det[dc] = rank;
                dc++;
                if (tid == grp) alive &= ~(1u << b);
                rem |= smask[rank * 32 + tid];
            }
            if (tid == 0) s_dc = dc;
        }
        __syncthreads();
        int dc = s_dc;
        int lane = tid & 31;
        int w = tid >> 5;
        for (int d = w; d < MAXDET; d += 32) {
            if (d < dc) {
                int rank = s_det[d];
                unsigned idx = g_ridx[rank];
                const float* row = cls + (size_t)idx * C;
                float bv = -3.402823466e38f; int bi = 0;
                for (int c = lane; c < C; c += 32) {
                    float v = row[c];
                    if (v > bv) { bv = v; bi = c; }
                }
                #pragma unroll
                for (int o = 16; o; o >>= 1) {
                    float ov = __shfl_down_sync(0xFFFFFFFFu, bv, o);
                    int   oi = __shfl_down_sync(0xFFFFFFFFu, bi, o);
                    if (ov > bv || (ov == bv && oi < bi)) { bv = ov; bi = oi; }
                }
                if (lane == 0) {
                    out[d] = g_rscore[rank];
                    out[100 + d] = (float)bi;
                    out[200 + 4 * d + 0] = g_rbox[4 * rank + 0];
                    out[200 + 4 * d + 1] = g_rbox[4 * rank + 1];
                    out[200 + 4 * d + 2] = g_rbox[4 * rank + 2];
                    out[200 + 4 * d + 3] = g_rbox[4 * rank + 3];
                }
            } else if (lane == 0) {
                out[d] = 0.0f;
                out[100 + d] = -1.0f;
                out[200 + 4 * d + 0] = 0.0f; out[200 + 4 * d + 1] = 0.0f;
                out[200 + 4 * d + 2] = 0.0f; out[200 + 4 * d + 3] = 0.0f;
            }
        }
        if (tid == 0) { g_candCount = 0; g_tieCount = 0; }
    }
}

// ---------------- host launcher ----------------
extern "C" void kernel_launch(void* const* d_in, const int* in_sizes, int n_in,
                              void* d_out, int out_size) {
    const float* cls = (const float*)d_in[0];
    const float* reg = (const float*)d_in[1];
    const float* anc = (const float*)d_in[2];
    const int* ih = (const int*)d_in[3];
    const int* iw = (const int*)d_in[4];

    int A = in_sizes[1] / 4;
    int C = (A > 0) ? (in_sizes[0] / A) : 80;
    float* out = (float*)d_out;
    (void)out_size; (void)n_in;

    cudaFuncSetAttribute(fused, cudaFuncAttributeMaxDynamicSharedMemorySize, DSMEM_BYTES);
    fused<<<NBLK, NTHR, DSMEM_BYTES>>>(cls, reg, anc, ih, iw, out, A, C);
}